// round 13
// baseline (speedup 1.0000x reference)
#include <cuda_runtime.h>
#include <cuda_bf16.h>
#include <cstdint>

#define NHEADS   8
#define DK       64
#define SEQ      1024
#define BATCH    8
#define DMODEL   512
#define BHD      (BATCH*NHEADS)          // 64
#define TOKENS   (BATCH*SEQ)             // 8192
#define QKV_ELEMS (BHD*SEQ*DK)           // 4194304
#define XW_ELEMS (TOKENS*DMODEL)         // 4194304

// ---------------- scratch (device globals; no allocation allowed) ----------
__device__ float g_q[QKV_ELEMS];
__device__ float g_k[QKV_ELEMS];
__device__ float g_v[QKV_ELEMS];
__device__ float g_nq[QKV_ELEMS];
__device__ float g_ssq;
__device__ int   g_cur;                  // 0: current q in g_q, 1: in g_nq

// bf16 hi/lo splits (built per launch)
__device__ __align__(256) __nv_bfloat16 gk_hi[QKV_ELEMS];   // K, K-major
__device__ __align__(256) __nv_bfloat16 gk_lo[QKV_ELEMS];
__device__ __align__(256) __nv_bfloat16 gkt_hi[QKV_ELEMS];  // K^T, d-major
__device__ __align__(256) __nv_bfloat16 gkt_lo[QKV_ELEMS];
__device__ __align__(256) __nv_bfloat16 gvt_hi[QKV_ELEMS];  // V^T, d-major
__device__ __align__(256) __nv_bfloat16 gvt_lo[QKV_ELEMS];
__device__ __align__(256) __nv_bfloat16 gx_hi[XW_ELEMS];    // x, row-major
__device__ __align__(256) __nv_bfloat16 gx_lo[XW_ELEMS];
__device__ __align__(256) __nv_bfloat16 gw_hi[4*DMODEL*DMODEL]; // W^T [n][k]
__device__ __align__(256) __nv_bfloat16 gw_lo[4*DMODEL*DMODEL];
__device__ __align__(256) __nv_bfloat16 go_hi[XW_ELEMS];    // attn out gathered
__device__ __align__(256) __nv_bfloat16 go_lo[XW_ELEMS];

// ---------------- helpers ----------------------------------------------------
__device__ __forceinline__ void hilo(float x, float& h, float& l) {
    h = __bfloat162float(__float2bfloat16(x));
    l = x - h;
}
// Truncation split of a pair: hp = {bf16_trunc(a), bf16_trunc(b)} via PRMT,
// lp = {bf16_rn(a-hi_a), bf16_rn(b-hi_b)} via one cvt.rn.bf16x2.
__device__ __forceinline__ void split2(float a, float b,
                                       uint32_t& hp, uint32_t& lp) {
    uint32_t ua = __float_as_uint(a), ub = __float_as_uint(b);
    float ha = __uint_as_float(ua & 0xFFFF0000u);
    float hb = __uint_as_float(ub & 0xFFFF0000u);
    asm("prmt.b32 %0, %1, %2, 0x7632;" : "=r"(hp) : "r"(ua), "r"(ub));
    float la = a - ha, lb = b - hb;
    asm("cvt.rn.bf16x2.f32 %0, %1, %2;" : "=r"(lp) : "f"(lb), "f"(la));
}
// m16n8k16 bf16 MMA, f32 accumulate (sm_80 baseline PTX -> HMMA on sm_103a)
__device__ __forceinline__ void mma16816(float c[4], const uint32_t a[4],
                                         uint32_t b0, uint32_t b1) {
    asm volatile(
        "mma.sync.aligned.m16n8k16.row.col.f32.bf16.bf16.f32 "
        "{%0,%1,%2,%3}, {%4,%5,%6,%7}, {%8,%9}, {%0,%1,%2,%3};"
        : "+f"(c[0]), "+f"(c[1]), "+f"(c[2]), "+f"(c[3])
        : "r"(a[0]), "r"(a[1]), "r"(a[2]), "r"(a[3]), "r"(b0), "r"(b1));
}
// ldmatrix x4 (non-transposed, b16)
#define LDSM4(r0, r1, r2, r3, addr) \
    asm volatile("ldmatrix.sync.aligned.m8n8.x4.shared.b16 {%0,%1,%2,%3}, [%4];" \
                 : "=r"(r0), "=r"(r1), "=r"(r2), "=r"(r3) : "r"(addr))
// cp.async 16B (sm_80 baseline)
#define CPA16(dst_u32, src_ptr) \
    asm volatile("cp.async.cg.shared.global [%0], [%1], 16;" \
                 :: "r"(dst_u32), "l"(src_ptr))
#define CPA_COMMIT() asm volatile("cp.async.commit_group;" ::: "memory")
#define CPA_WAIT0()  asm volatile("cp.async.wait_group 0;" ::: "memory")

__device__ __forceinline__ uint32_t smem_addr_u32(const void* p) {
    uint32_t a;
    asm("{ .reg .u64 t; cvta.to.shared.u64 t, %1; cvt.u32.u64 %0, t; }"
        : "=r"(a) : "l"(p));
    return a;
}

#define KSTR 72   // smem row stride in bf16 (144 B) -> conflict-free fragments

// ---------------------------------------------------------------------------
// prep_x: split x into bf16 hi/lo (row-major).
// ---------------------------------------------------------------------------
__global__ __launch_bounds__(256)
void prep_x(const float* __restrict__ x)
{
    int i = (blockIdx.x * 256 + threadIdx.x) * 4;
    float4 v = *(const float4*)(x + i);
    uint32_t h01, l01, h23, l23;
    split2(v.x, v.y, h01, l01);
    split2(v.z, v.w, h23, l23);
    *(uint32_t*)&gx_hi[i]     = h01;
    *(uint32_t*)&gx_hi[i + 2] = h23;
    *(uint32_t*)&gx_lo[i]     = l01;
    *(uint32_t*)&gx_lo[i + 2] = l23;
}

// ---------------------------------------------------------------------------
// prep_w: transpose each W (k-major 512x512) into [n][k] and split hi/lo.
// ---------------------------------------------------------------------------
__global__ __launch_bounds__(256)
void prep_w(const float* __restrict__ Wq, const float* __restrict__ Wk,
            const float* __restrict__ Wv, const float* __restrict__ Wo)
{
    __shared__ float tile[64][65];
    const int z = blockIdx.z;
    const float* W = (z == 0) ? Wq : (z == 1) ? Wk : (z == 2) ? Wv : Wo;
    const int k0 = blockIdx.x * 64, n0 = blockIdx.y * 64;
    const int tid = threadIdx.x;

    for (int idx = tid; idx < 4096; idx += 256) {
        int r = idx >> 6, c = idx & 63;
        tile[r][c] = W[(size_t)(k0 + r) * DMODEL + n0 + c];
    }
    __syncthreads();
    for (int idx = tid * 2; idx < 4096; idx += 512) {
        int r = idx >> 6, c = idx & 63;           // r: n-local, c: k-local
        uint32_t hp, lp;
        split2(tile[c][r], tile[c + 1][r], hp, lp);
        size_t o = (size_t)z * DMODEL * DMODEL + (size_t)(n0 + r) * DMODEL + k0 + c;
        *(uint32_t*)&gw_hi[o] = hp;
        *(uint32_t*)&gw_lo[o] = lp;
    }
}

// ---------------------------------------------------------------------------
// Generic SMEM-staged HMMA projection body (R10, passing — unchanged).
// ---------------------------------------------------------------------------
struct ProjSmem {
    __nv_bfloat16 xhi[128 * KSTR];
    __nv_bfloat16 xlo[128 * KSTR];
    __nv_bfloat16 whi[64 * KSTR];
    __nv_bfloat16 wlo[64 * KSTR];
};

__device__ __forceinline__ void proj_tiles_mma(
    ProjSmem* s,
    const __nv_bfloat16* __restrict__ ahi, const __nv_bfloat16* __restrict__ alo,
    const __nv_bfloat16* __restrict__ bhi, const __nv_bfloat16* __restrict__ blo,
    int row0, int n0, float acc[8][4])
{
    const int tid = threadIdx.x;
    const int warp = tid >> 5, lane = tid & 31;
    const int g = lane >> 2, t = lane & 3;
    const int m0 = warp * 16;
    const int lrow = tid >> 2, lseg = (tid & 3) * 16;

    for (int kt = 0; kt < DMODEL / 64; kt++) {
        const int k0 = kt * 64;
        __syncthreads();
        #pragma unroll
        for (int half = 0; half < 2; half++) {
            int xr = half * 64 + lrow;
            size_t gx = (size_t)(row0 + xr) * DMODEL + k0 + lseg;
            uint32_t so = xr * KSTR + lseg;
            *(uint4*)&s->xhi[so]     = *(const uint4*)(ahi + gx);
            *(uint4*)&s->xhi[so + 8] = *(const uint4*)(ahi + gx + 8);
            *(uint4*)&s->xlo[so]     = *(const uint4*)(alo + gx);
            *(uint4*)&s->xlo[so + 8] = *(const uint4*)(alo + gx + 8);
        }
        {
            size_t gw = (size_t)(n0 + lrow) * DMODEL + k0 + lseg;
            uint32_t so = lrow * KSTR + lseg;
            *(uint4*)&s->whi[so]     = *(const uint4*)(bhi + gw);
            *(uint4*)&s->whi[so + 8] = *(const uint4*)(bhi + gw + 8);
            *(uint4*)&s->wlo[so]     = *(const uint4*)(blo + gw);
            *(uint4*)&s->wlo[so + 8] = *(const uint4*)(blo + gw + 8);
        }
        __syncthreads();

        #pragma unroll
        for (int kk = 0; kk < 4; kk++) {
            const int kc = 16 * kk + 2 * t;
            uint32_t ah[4], al[4];
            ah[0] = *(const uint32_t*)&s->xhi[(m0 + g) * KSTR + kc];
            ah[1] = *(const uint32_t*)&s->xhi[(m0 + g + 8) * KSTR + kc];
            ah[2] = *(const uint32_t*)&s->xhi[(m0 + g) * KSTR + kc + 8];
            ah[3] = *(const uint32_t*)&s->xhi[(m0 + g + 8) * KSTR + kc + 8];
            al[0] = *(const uint32_t*)&s->xlo[(m0 + g) * KSTR + kc];
            al[1] = *(const uint32_t*)&s->xlo[(m0 + g + 8) * KSTR + kc];
            al[2] = *(const uint32_t*)&s->xlo[(m0 + g) * KSTR + kc + 8];
            al[3] = *(const uint32_t*)&s->xlo[(m0 + g + 8) * KSTR + kc + 8];
            #pragma unroll
            for (int j = 0; j < 8; j++) {
                const int n = 8 * j + g;
                uint32_t bh0 = *(const uint32_t*)&s->whi[n * KSTR + kc];
                uint32_t bh1 = *(const uint32_t*)&s->whi[n * KSTR + kc + 8];
                uint32_t bl0 = *(const uint32_t*)&s->wlo[n * KSTR + kc];
                uint32_t bl1 = *(const uint32_t*)&s->wlo[n * KSTR + kc + 8];
                mma16816(acc[j], ah, bh0, bh1);
                mma16816(acc[j], al, bh0, bh1);
                mma16816(acc[j], ah, bl0, bl1);
            }
        }
    }
}

// ---------------------------------------------------------------------------
// QKV projection via SMEM-staged HMMA + fused LayerNorm (q,k). (R10.)
// ---------------------------------------------------------------------------
__global__ __launch_bounds__(256)
void qkv_mma(const float* __restrict__ bq, const float* __restrict__ bk,
             const float* __restrict__ bv,
             const float* __restrict__ gamma, const float* __restrict__ beta)
{
    extern __shared__ char smraw[];
    ProjSmem* s = (ProjSmem*)smraw;

    const int mat  = blockIdx.y >> 3;
    const int head = blockIdx.y & 7;
    const int row0 = blockIdx.x * 128;
    const int tid = threadIdx.x;
    const int warp = tid >> 5, lane = tid & 31;
    const int g = lane >> 2, t = lane & 3;
    const int m0 = warp * 16;

    const float* bias = (mat == 0) ? bq : (mat == 1) ? bk : bv;
    float*       out  = (mat == 0) ? g_q : (mat == 1) ? g_k : g_v;
    const __nv_bfloat16* wh = gw_hi + (size_t)mat * DMODEL * DMODEL + (size_t)head * 64 * DMODEL;
    const __nv_bfloat16* wl = gw_lo + (size_t)mat * DMODEL * DMODEL + (size_t)head * 64 * DMODEL;

    float acc[8][4];
    #pragma unroll
    for (int j = 0; j < 8; j++)
        #pragma unroll
        for (int i = 0; i < 4; i++) acc[j][i] = 0.f;

    proj_tiles_mma(s, gx_hi, gx_lo, wh, wl, row0, 0, acc);

    #pragma unroll
    for (int j = 0; j < 8; j++) {
        float b0v = bias[head * 64 + 8 * j + 2 * t];
        float b1v = bias[head * 64 + 8 * j + 2 * t + 1];
        acc[j][0] += b0v; acc[j][1] += b1v;
        acc[j][2] += b0v; acc[j][3] += b1v;
    }

    if (mat < 2) {
        float s0 = 0.f, s1 = 0.f;
        #pragma unroll
        for (int j = 0; j < 8; j++) {
            s0 += acc[j][0] + acc[j][1];
            s1 += acc[j][2] + acc[j][3];
        }
        s0 += __shfl_xor_sync(~0u, s0, 1); s0 += __shfl_xor_sync(~0u, s0, 2);
        s1 += __shfl_xor_sync(~0u, s1, 1); s1 += __shfl_xor_sync(~0u, s1, 2);
        float mu0 = s0 * (1.f / 64.f), mu1 = s1 * (1.f / 64.f);
        float v0 = 0.f, v1 = 0.f;
        #pragma unroll
        for (int j = 0; j < 8; j++) {
            acc[j][0] -= mu0; acc[j][1] -= mu0;
            acc[j][2] -= mu1; acc[j][3] -= mu1;
            v0 += acc[j][0] * acc[j][0] + acc[j][1] * acc[j][1];
            v1 += acc[j][2] * acc[j][2] + acc[j][3] * acc[j][3];
        }
        v0 += __shfl_xor_sync(~0u, v0, 1); v0 += __shfl_xor_sync(~0u, v0, 2);
        v1 += __shfl_xor_sync(~0u, v1, 1); v1 += __shfl_xor_sync(~0u, v1, 2);
        float inv0 = rsqrtf(v0 * (1.f / 64.f) + 1e-5f);
        float inv1 = rsqrtf(v1 * (1.f / 64.f) + 1e-5f);
        #pragma unroll
        for (int j = 0; j < 8; j++) {
            float ga0 = gamma[8 * j + 2 * t], ga1 = gamma[8 * j + 2 * t + 1];
            float be0 = beta[8 * j + 2 * t],  be1 = beta[8 * j + 2 * t + 1];
            acc[j][0] = acc[j][0] * inv0 * ga0 + be0;
            acc[j][1] = acc[j][1] * inv0 * ga1 + be1;
            acc[j][2] = acc[j][2] * inv1 * ga0 + be0;
            acc[j][3] = acc[j][3] * inv1 * ga1 + be1;
        }
    }

    const int r0 = row0 + m0 + g, r1 = r0 + 8;
    const int b0i = r0 >> 10, ss0 = r0 & 1023;
    const int b1i = r1 >> 10, ss1 = r1 & 1023;
    float* o0 = out + (((size_t)b0i * NHEADS + head) * SEQ + ss0) * DK;
    float* o1 = out + (((size_t)b1i * NHEADS + head) * SEQ + ss1) * DK;
    #pragma unroll
    for (int j = 0; j < 8; j++) {
        *(float2*)(o0 + 8 * j + 2 * t) = make_float2(acc[j][0], acc[j][1]);
        *(float2*)(o1 + 8 * j + 2 * t) = make_float2(acc[j][2], acc[j][3]);
    }
}

// ---------------------------------------------------------------------------
// Output projection via SMEM-staged HMMA. (R10.)
// ---------------------------------------------------------------------------
__global__ __launch_bounds__(256)
void out_mma(const float* __restrict__ bo, float* __restrict__ C)
{
    extern __shared__ char smraw[];
    ProjSmem* s = (ProjSmem*)smraw;

    const int n0   = blockIdx.y * 64;
    const int row0 = blockIdx.x * 128;
    const int tid = threadIdx.x;
    const int warp = tid >> 5, lane = tid & 31;
    const int g = lane >> 2, t = lane & 3;
    const int m0 = warp * 16;

    const __nv_bfloat16* wh = gw_hi + (size_t)3 * DMODEL * DMODEL;
    const __nv_bfloat16* wl = gw_lo + (size_t)3 * DMODEL * DMODEL;

    float acc[8][4];
    #pragma unroll
    for (int j = 0; j < 8; j++)
        #pragma unroll
        for (int i = 0; i < 4; i++) acc[j][i] = 0.f;

    proj_tiles_mma(s, go_hi, go_lo, wh, wl, row0, n0, acc);

    const int r0 = row0 + m0 + g, r1 = r0 + 8;
    #pragma unroll
    for (int j = 0; j < 8; j++) {
        float b0v = bo[n0 + 8 * j + 2 * t];
        float b1v = bo[n0 + 8 * j + 2 * t + 1];
        *(float2*)(C + (size_t)r0 * DMODEL + n0 + 8 * j + 2 * t) =
            make_float2(acc[j][0] + b0v, acc[j][1] + b1v);
        *(float2*)(C + (size_t)r1 * DMODEL + n0 + 8 * j + 2 * t) =
            make_float2(acc[j][2] + b0v, acc[j][3] + b1v);
    }
}

// ---------------------------------------------------------------------------
// Prep: split K -> bf16 hi/lo (K-major), and K^T, V^T -> bf16 hi/lo (d-major).
// ---------------------------------------------------------------------------
__global__ __launch_bounds__(256)
void prep_kernel()
{
    __shared__ float ts[64][65];
    const int bh = blockIdx.y;
    const int s0 = blockIdx.x * 64;
    const int tid = threadIdx.x;

    for (int idx = tid; idx < 4096; idx += 256) {
        int r = idx >> 6, d = idx & 63;
        float x = g_k[((size_t)bh * SEQ + s0 + r) * DK + d];
        float h, l; hilo(x, h, l);
        size_t o = ((size_t)bh * SEQ + s0 + r) * DK + d;
        gk_hi[o] = __float2bfloat16(h);
        gk_lo[o] = __float2bfloat16(l);
        ts[r][d] = x;
    }
    __syncthreads();
    for (int idx = tid; idx < 4096; idx += 256) {
        int d = idx >> 6, s = idx & 63;
        float x = ts[s][d];
        float h, l; hilo(x, h, l);
        size_t o = ((size_t)bh * DK + d) * SEQ + s0 + s;
        gkt_hi[o] = __float2bfloat16(h);
        gkt_lo[o] = __float2bfloat16(l);
    }
    __syncthreads();
    for (int idx = tid; idx < 4096; idx += 256) {
        int r = idx >> 6, d = idx & 63;
        ts[r][d] = g_v[((size_t)bh * SEQ + s0 + r) * DK + d];
    }
    __syncthreads();
    for (int idx = tid; idx < 4096; idx += 256) {
        int d = idx >> 6, s = idx & 63;
        float x = ts[s][d];
        float h, l; hilo(x, h, l);
        size_t o = ((size_t)bh * DK + d) * SEQ + s0 + s;
        gvt_hi[o] = __float2bfloat16(h);
        gvt_lo[o] = __float2bfloat16(l);
    }
}

// ---------------------------------------------------------------------------
// Attention: low-register variant for 3 CTAs/SM.
// Q tile hi/lo staged in SMEM (A-frags via ldmatrix, not register-resident);
// each 64-key tile processed in two 32-key halves (smaller live sets).
// Buffer ping-pong: q source/dest selected by g_cur at runtime.
// grid = (SEQ/128, BHD), 256 threads, dyn smem 73728 B, 3 CTAs/SM target.
// ---------------------------------------------------------------------------
#define TILE_B   9216            // 64*KSTR*2 bytes
#define QREG_B   (2*128*KSTR*2)  // Q hi+lo: 36864
#define KV_B     (4*TILE_B)      // khi,klo,vhi,vlo: 36864
#define ATTN_SMEM (QREG_B + KV_B)  // 73728

__global__ __launch_bounds__(256, 3)
void attn_mma(int finalPass)
{
    extern __shared__ char smraw[];
    const uint32_t sbase = smem_addr_u32(smraw);
    const uint32_t qlo_off = 128 * KSTR * 2;     // 18432
    const uint32_t kv_off  = QREG_B;             // 36864

    const int tid  = threadIdx.x;
    const int lane = tid & 31;
    const int g = lane >> 2;
    const int t = lane & 3;
    const int bh = blockIdx.y;
    const int q0 = blockIdx.x * 128;
    const int m0 = (tid >> 5) * 16;

    const int cur = g_cur;
    const float* qsrc = cur ? g_nq : g_q;
    float*       qdst = cur ? g_q : g_nq;
    const float* qb = qsrc + ((size_t)bh * SEQ + q0) * DK;

    // ---- stage Q tile (hi/lo) into SMEM: thread = (row tid/2, col-half) ----
    {
        const int qr = tid >> 1;
        const int ch = (tid & 1) * 32;
        const float4* src = (const float4*)(qb + (size_t)qr * DK + ch);
        uint32_t so = (qr * KSTR + ch) * 2;
        #pragma unroll
        for (int c = 0; c < 4; c++) {
            float4 a = src[2 * c];
            float4 b = src[2 * c + 1];
            uint32_t h0, l0, h1, l1, h2, l2, h3, l3;
            split2(a.x, a.y, h0, l0); split2(a.z, a.w, h1, l1);
            split2(b.x, b.y, h2, l2); split2(b.z, b.w, h3, l3);
            uint4 hv = make_uint4(h0, h1, h2, h3);
            uint4 lv = make_uint4(l0, l1, l2, l3);
            *(uint4*)(smraw + so + c * 16)           = hv;
            *(uint4*)(smraw + so + qlo_off + c * 16) = lv;
        }
    }

    // ldmatrix lane offsets
    //  A-frags (16 rows x 16 cols): addr = (m0 + (lane&15))*KSTR*2 + (lane>>4)*16
    const uint32_t aoff = (uint32_t)((m0 + (lane & 15)) * KSTR * 2)
                        + (uint32_t)((lane >> 4) * 16);
    //  B-frags (x4: hi0,hi1,lo0,lo1): rows lane&7, quad sel -> col-half/region
    const int qsel = lane >> 3, rsel = lane & 7;
    const uint32_t boff = (uint32_t)(rsel * KSTR * 2)
                        + (uint32_t)((qsel & 1) * 16)
                        + (uint32_t)((qsel >> 1) * TILE_B);

    float oc[8][4];
    #pragma unroll
    for (int j = 0; j < 8; j++)
        #pragma unroll
        for (int i = 0; i < 4; i++) oc[j][i] = 0.f;
    float lac0 = 0.f, lac1 = 0.f;

    const __nv_bfloat16* pkhi = gk_hi + (size_t)bh * SEQ * DK;
    const __nv_bfloat16* pklo = gk_lo + (size_t)bh * SEQ * DK;
    const __nv_bfloat16* pbhi = (finalPass ? gvt_hi : gkt_hi) + (size_t)bh * DK * SEQ;
    const __nv_bfloat16* pblo = (finalPass ? gvt_lo : gkt_lo) + (size_t)bh * DK * SEQ;

    const int lrow = tid >> 2;             // 0..63
    const int lseg = (tid & 3) * 16;       // bf16 col offset
    const uint32_t soB = kv_off + (uint32_t)(lrow * KSTR + lseg) * 2;

    const uint32_t qhi_base = sbase;
    const uint32_t qlo_base = sbase + qlo_off;
    const uint32_t kbase = sbase + kv_off + boff;            // K hi/lo
    const uint32_t vbase = kbase + 2 * TILE_B;               // V hi/lo

    for (int kt64 = 0; kt64 < SEQ / 64; kt64++) {
        // (first iteration: also orders the Q staging writes)
        __syncthreads();
        {
            uint32_t b = sbase + soB;
            size_t gk = ((size_t)(kt64 * 64 + lrow)) * DK + lseg;
            size_t gb = (size_t)lrow * SEQ + kt64 * 64 + lseg;
            CPA16(b,                     pkhi + gk);
            CPA16(b + 16,                pkhi + gk + 8);
            CPA16(b + TILE_B,            pklo + gk);
            CPA16(b + TILE_B + 16,       pklo + gk + 8);
            CPA16(b + 2 * TILE_B,        pbhi + gb);
            CPA16(b + 2 * TILE_B + 16,   pbhi + gb + 8);
            CPA16(b + 3 * TILE_B,        pblo + gb);
            CPA16(b + 3 * TILE_B + 16,   pblo + gb + 8);
        }
        CPA_COMMIT();
        CPA_WAIT0();
        __syncthreads();

        #pragma unroll
        for (int h = 0; h < 2; h++) {
            // ---- S half: keys 32h .. 32h+31 ----
            float sc[4][4];
            #pragma unroll
            for (int j = 0; j < 4; j++)
                #pragma unroll
                for (int i = 0; i < 4; i++) sc[j][i] = 0.f;

            #pragma unroll
            for (int kk = 0; kk < 4; kk++) {
                uint32_t ah[4], al[4];
                LDSM4(ah[0], ah[1], ah[2], ah[3], qhi_base + aoff + kk * 32);
                LDSM4(al[0], al[1], al[2], al[3], qlo_base + aoff + kk * 32);
                #pragma unroll
                for (int j = 0; j < 4; j++) {
                    uint32_t ka = kbase
                        + (uint32_t)((4 * h + j) * 8 * KSTR * 2) + kk * 32;
                    uint32_t b0, b1, b2, b3;
                    LDSM4(b0, b1, b2, b3, ka);
                    mma16816(sc[j], ah, b0, b1);
                    mma16816(sc[j], al, b0, b1);
                    mma16816(sc[j], ah, b2, b3);
                }
            }

            // ---- softmax half: p = 2^(s*0.125*log2e - 8*log2e) ----
            uint32_t pah[2][4], pal[2][4];
            #pragma unroll
            for (int kk = 0; kk < 2; kk++) {
                float e0a = exp2f(fmaf(sc[2*kk][0],   0.180336880f, -11.5416355f));
                float e0b = exp2f(fmaf(sc[2*kk][1],   0.180336880f, -11.5416355f));
                float e0c = exp2f(fmaf(sc[2*kk][2],   0.180336880f, -11.5416355f));
                float e0d = exp2f(fmaf(sc[2*kk][3],   0.180336880f, -11.5416355f));
                float e1a = exp2f(fmaf(sc[2*kk+1][0], 0.180336880f, -11.5416355f));
                float e1b = exp2f(fmaf(sc[2*kk+1][1], 0.180336880f, -11.5416355f));
                float e1c = exp2f(fmaf(sc[2*kk+1][2], 0.180336880f, -11.5416355f));
                float e1d = exp2f(fmaf(sc[2*kk+1][3], 0.180336880f, -11.5416355f));
                lac0 += e0a + e0b + e1a + e1b;
                lac1 += e0c + e0d + e1c + e1d;
                split2(e0a, e0b, pah[kk][0], pal[kk][0]);
                split2(e0c, e0d, pah[kk][1], pal[kk][1]);
                split2(e1a, e1b, pah[kk][2], pal[kk][2]);
                split2(e1c, e1d, pah[kk][3], pal[kk][3]);
            }

            // ---- PV half: O += P[:,32h..] @ Vals[32h..,:] ----
            #pragma unroll
            for (int j = 0; j < 8; j++) {
                uint32_t va = vbase + (uint32_t)(j * 8 * KSTR * 2);
                #pragma unroll
                for (int kkp = 0; kkp < 2; kkp++) {
                    uint32_t b0, b1, b2, b3;
                    LDSM4(b0, b1, b2, b3, va + (2 * h + kkp) * 32);
                    mma16816(oc[j], pah[kkp], b0, b1);
                    mma16816(oc[j], pal[kkp], b0, b1);
                    mma16816(oc[j], pah[kkp], b2, b3);
                }
            }
        }
        __syncthreads();   // all reads done before KV refill
    }

    // ---- epilogue: normalize, store, ssq ----
    lac0 += __shfl_xor_sync(~0u, lac0, 1);
    lac0 += __shfl_xor_sync(~0u, lac0, 2);
    lac1 += __shfl_xor_sync(~0u, lac1, 1);
    lac1 += __shfl_xor_sync(~0u, lac1, 2);
    const float inv0 = 1.0f / lac0;
    const float inv1 = 1.0f / lac1;

    float* ob0 = qdst + ((size_t)bh * SEQ + q0 + m0 + g) * DK;
    float* ob1 = qdst + ((size_t)bh * SEQ + q0 + m0 + g + 8) * DK;
    const float* qr0 = qb + (size_t)(m0 + g) * DK;
    const float* qr1 = qb + (size_t)(m0 + g + 8) * DK;
    float local = 0.f;
    #pragma unroll
    for (int j = 0; j < 8; j++) {
        int c = 8 * j + 2 * t;
        float2 w0 = make_float2(oc[j][0] * inv0, oc[j][1] * inv0);
        float2 w1 = make_float2(oc[j][2] * inv1, oc[j][3] * inv1);
        *(float2*)(ob0 + c) = w0;
        *(float2*)(ob1 + c) = w1;
        if (!finalPass) {
            float2 a = *(const float2*)(qr0 + c);
            float2 b = *(const float2*)(qr1 + c);
            float d0 = w0.x - a.x, d1 = w0.y - a.y;
            float d2 = w1.x - b.x, d3 = w1.y - b.y;
            local += d0 * d0 + d1 * d1 + d2 * d2 + d3 * d3;
        }
    }
    if (!finalPass) {
        #pragma unroll
        for (int off = 16; off; off >>= 1)
            local += __shfl_xor_sync(~0u, local, off);
        if (lane == 0) atomicAdd(&g_ssq, local);
    }
}

// ---------------------------------------------------------------------------
__global__ void init_state_kernel() { g_cur = 0; g_ssq = 0.0f; }

// eps gate: flip current-q buffer iff ||new_q - q|| > 1e-4; reset ssq.
__global__ void gate_flip_kernel()
{
    if (g_ssq > 1e-8f) g_cur ^= 1;
    g_ssq = 0.0f;
}

// ---------------------------------------------------------------------------
// prep_o: gather final attn output -> go hi/lo [token][512] row-major.
// Final O lives in the buffer OPPOSITE to g_cur.
// ---------------------------------------------------------------------------
__global__ __launch_bounds__(256)
void prep_o()
{
    const float* src = g_cur ? g_q : g_nq;
    int i4 = blockIdx.x * 256 + threadIdx.x;
    int dq = (i4 & 15) * 4;
    int tk = i4 >> 4;
    float4 v = *(const float4*)(src + (size_t)tk * DK + dq);
    int bh = tk >> 10, s = tk & 1023;
    int b = bh >> 3, h = bh & 7;
    size_t o = ((size_t)(b * SEQ + s)) * DMODEL + h * 64 + dq;
    uint32_t h01, l01, h23, l23;
    split2(v.x, v.y, h01, l01);
    split2(v.z, v.w, h23, l23);
    *(uint32_t*)&go_hi[o]     = h01;
    *(uint32_t*)&go_hi[o + 2] = h23;
    *(uint32_t*)&go_lo[o]     = l01;
    *(uint32_t*)&go_lo[o + 2] = l23;
}

// ---------------------------------------------------------------------------
extern "C" void kernel_launch(void* const* d_in, const int* in_sizes, int n_in,
                              void* d_out, int out_size)
{
    const float* x     = (const float*)d_in[0];
    const float* Wq    = (const float*)d_in[1];
    const float* bq    = (const float*)d_in[2];
    const float* Wk    = (const float*)d_in[3];
    const float* bk    = (const float*)d_in[4];
    const float* Wv    = (const float*)d_in[5];
    const float* bv    = (const float*)d_in[6];
    const float* Wo    = (const float*)d_in[7];
    const float* bo    = (const float*)d_in[8];
    const float* gamma = (const float*)d_in[9];
    const float* beta  = (const float*)d_in[10];
    float* out = (float*)d_out;

    const int projSmem = (int)sizeof(ProjSmem);   // 55296 B
    cudaFuncSetAttribute(qkv_mma,
                         cudaFuncAttributeMaxDynamicSharedMemorySize, projSmem);
    cudaFuncSetAttribute(out_mma,
                         cudaFuncAttributeMaxDynamicSharedMemorySize, projSmem);
    cudaFuncSetAttribute(attn_mma,
                         cudaFuncAttributeMaxDynamicSharedMemorySize, ATTN_SMEM);

    // 0. state init + hi/lo splits of x and W^T
    init_state_kernel<<<1, 1>>>();
    prep_x<<<XW_ELEMS / 4 / 256, 256>>>(x);
    prep_w<<<dim3(8, 8, 4), 256>>>(Wq, Wk, Wv, Wo);
    // 1. QKV projections via SMEM-staged HMMA (+ fused LayerNorm for q,k)
    qkv_mma<<<dim3(TOKENS / 128, 24), 256, projSmem>>>(bq, bk, bv, gamma, beta);
    // 2. bf16 hi/lo splits of K, K^T, V^T
    prep_kernel<<<dim3(SEQ / 64, BHD), 256>>>();
    // 3. Hopfield update iterations (values = K), buffer ping-pong eps gate
    for (int it = 0; it < 3; it++) {
        attn_mma<<<dim3(SEQ / 128, BHD), 256, ATTN_SMEM>>>(0);
        gate_flip_kernel<<<1, 1>>>();
    }
    // 4. Final retrieval (values = V)
    attn_mma<<<dim3(SEQ / 128, BHD), 256, ATTN_SMEM>>>(1);
    // 5. Output projection via SMEM-staged HMMA
    prep_o<<<XW_ELEMS / 4 / 256, 256>>>();
    out_mma<<<dim3(TOKENS / 128, 8), 256, projSmem>>>(bo, out);
}

// round 14
// speedup vs baseline: 1.1849x; 1.1849x over previous
#include <cuda_runtime.h>
#include <cuda_bf16.h>
#include <cstdint>

#define NHEADS   8
#define DK       64
#define SEQ      1024
#define BATCH    8
#define DMODEL   512
#define BHD      (BATCH*NHEADS)          // 64
#define TOKENS   (BATCH*SEQ)             // 8192
#define QKV_ELEMS (BHD*SEQ*DK)           // 4194304
#define XW_ELEMS (TOKENS*DMODEL)         // 4194304

// ---------------- scratch (device globals; no allocation allowed) ----------
__device__ float g_q[QKV_ELEMS];
__device__ float g_k[QKV_ELEMS];
__device__ float g_v[QKV_ELEMS];
__device__ float g_nq[QKV_ELEMS];
__device__ float g_ssq;
__device__ int   g_cur;                  // 0: current q in g_q, 1: in g_nq

// bf16 hi/lo splits (built per launch)
__device__ __align__(256) __nv_bfloat16 gk_hi[QKV_ELEMS];   // K, K-major
__device__ __align__(256) __nv_bfloat16 gk_lo[QKV_ELEMS];
__device__ __align__(256) __nv_bfloat16 gkt_hi[QKV_ELEMS];  // K^T, d-major
__device__ __align__(256) __nv_bfloat16 gkt_lo[QKV_ELEMS];
__device__ __align__(256) __nv_bfloat16 gvt_hi[QKV_ELEMS];  // V^T, d-major
__device__ __align__(256) __nv_bfloat16 gvt_lo[QKV_ELEMS];
__device__ __align__(256) __nv_bfloat16 gx_hi[XW_ELEMS];    // x, row-major
__device__ __align__(256) __nv_bfloat16 gx_lo[XW_ELEMS];
__device__ __align__(256) __nv_bfloat16 gw_hi[4*DMODEL*DMODEL]; // W^T [n][k]
__device__ __align__(256) __nv_bfloat16 gw_lo[4*DMODEL*DMODEL];
__device__ __align__(256) __nv_bfloat16 go_hi[XW_ELEMS];    // attn out gathered
__device__ __align__(256) __nv_bfloat16 go_lo[XW_ELEMS];

// ---------------- helpers ----------------------------------------------------
__device__ __forceinline__ void hilo(float x, float& h, float& l) {
    h = __bfloat162float(__float2bfloat16(x));
    l = x - h;
}
// Truncation split of a pair: hp = {bf16_trunc(a), bf16_trunc(b)} via PRMT,
// lp = {bf16_rn(a-hi_a), bf16_rn(b-hi_b)} via one cvt.rn.bf16x2.
__device__ __forceinline__ void split2(float a, float b,
                                       uint32_t& hp, uint32_t& lp) {
    uint32_t ua = __float_as_uint(a), ub = __float_as_uint(b);
    float ha = __uint_as_float(ua & 0xFFFF0000u);
    float hb = __uint_as_float(ub & 0xFFFF0000u);
    asm("prmt.b32 %0, %1, %2, 0x7632;" : "=r"(hp) : "r"(ua), "r"(ub));
    float la = a - ha, lb = b - hb;
    asm("cvt.rn.bf16x2.f32 %0, %1, %2;" : "=r"(lp) : "f"(lb), "f"(la));
}
// m16n8k16 bf16 MMA, f32 accumulate (sm_80 baseline PTX -> HMMA on sm_103a)
__device__ __forceinline__ void mma16816(float c[4], const uint32_t a[4],
                                         uint32_t b0, uint32_t b1) {
    asm volatile(
        "mma.sync.aligned.m16n8k16.row.col.f32.bf16.bf16.f32 "
        "{%0,%1,%2,%3}, {%4,%5,%6,%7}, {%8,%9}, {%0,%1,%2,%3};"
        : "+f"(c[0]), "+f"(c[1]), "+f"(c[2]), "+f"(c[3])
        : "r"(a[0]), "r"(a[1]), "r"(a[2]), "r"(a[3]), "r"(b0), "r"(b1));
}
// cp.async 16B (sm_80 baseline)
#define CPA16(dst_u32, src_ptr) \
    asm volatile("cp.async.cg.shared.global [%0], [%1], 16;" \
                 :: "r"(dst_u32), "l"(src_ptr))
#define CPA_COMMIT() asm volatile("cp.async.commit_group;" ::: "memory")
#define CPA_WAIT1()  asm volatile("cp.async.wait_group 1;" ::: "memory")
#define CPA_WAIT0()  asm volatile("cp.async.wait_group 0;" ::: "memory")

__device__ __forceinline__ uint32_t smem_addr_u32(const void* p) {
    uint32_t a;
    asm("{ .reg .u64 t; cvta.to.shared.u64 t, %1; cvt.u32.u64 %0, t; }"
        : "=r"(a) : "l"(p));
    return a;
}

#define KSTR 72   // smem row stride in bf16 (144 B) -> conflict-free fragments

// ---------------------------------------------------------------------------
// prep_x: split x into bf16 hi/lo (row-major).
// ---------------------------------------------------------------------------
__global__ __launch_bounds__(256)
void prep_x(const float* __restrict__ x)
{
    int i = (blockIdx.x * 256 + threadIdx.x) * 4;
    float4 v = *(const float4*)(x + i);
    uint32_t h01, l01, h23, l23;
    split2(v.x, v.y, h01, l01);
    split2(v.z, v.w, h23, l23);
    *(uint32_t*)&gx_hi[i]     = h01;
    *(uint32_t*)&gx_hi[i + 2] = h23;
    *(uint32_t*)&gx_lo[i]     = l01;
    *(uint32_t*)&gx_lo[i + 2] = l23;
}

// ---------------------------------------------------------------------------
// prep_w: transpose each W (k-major 512x512) into [n][k] and split hi/lo.
// ---------------------------------------------------------------------------
__global__ __launch_bounds__(256)
void prep_w(const float* __restrict__ Wq, const float* __restrict__ Wk,
            const float* __restrict__ Wv, const float* __restrict__ Wo)
{
    __shared__ float tile[64][65];
    const int z = blockIdx.z;
    const float* W = (z == 0) ? Wq : (z == 1) ? Wk : (z == 2) ? Wv : Wo;
    const int k0 = blockIdx.x * 64, n0 = blockIdx.y * 64;
    const int tid = threadIdx.x;

    for (int idx = tid; idx < 4096; idx += 256) {
        int r = idx >> 6, c = idx & 63;
        tile[r][c] = W[(size_t)(k0 + r) * DMODEL + n0 + c];
    }
    __syncthreads();
    for (int idx = tid * 2; idx < 4096; idx += 512) {
        int r = idx >> 6, c = idx & 63;           // r: n-local, c: k-local
        uint32_t hp, lp;
        split2(tile[c][r], tile[c + 1][r], hp, lp);
        size_t o = (size_t)z * DMODEL * DMODEL + (size_t)(n0 + r) * DMODEL + k0 + c;
        *(uint32_t*)&gw_hi[o] = hp;
        *(uint32_t*)&gw_lo[o] = lp;
    }
}

// ---------------------------------------------------------------------------
// Generic SMEM-staged HMMA projection body (R10, passing — unchanged).
// ---------------------------------------------------------------------------
struct ProjSmem {
    __nv_bfloat16 xhi[128 * KSTR];
    __nv_bfloat16 xlo[128 * KSTR];
    __nv_bfloat16 whi[64 * KSTR];
    __nv_bfloat16 wlo[64 * KSTR];
};

__device__ __forceinline__ void proj_tiles_mma(
    ProjSmem* s,
    const __nv_bfloat16* __restrict__ ahi, const __nv_bfloat16* __restrict__ alo,
    const __nv_bfloat16* __restrict__ bhi, const __nv_bfloat16* __restrict__ blo,
    int row0, int n0, float acc[8][4])
{
    const int tid = threadIdx.x;
    const int warp = tid >> 5, lane = tid & 31;
    const int g = lane >> 2, t = lane & 3;
    const int m0 = warp * 16;
    const int lrow = tid >> 2, lseg = (tid & 3) * 16;

    for (int kt = 0; kt < DMODEL / 64; kt++) {
        const int k0 = kt * 64;
        __syncthreads();
        #pragma unroll
        for (int half = 0; half < 2; half++) {
            int xr = half * 64 + lrow;
            size_t gx = (size_t)(row0 + xr) * DMODEL + k0 + lseg;
            uint32_t so = xr * KSTR + lseg;
            *(uint4*)&s->xhi[so]     = *(const uint4*)(ahi + gx);
            *(uint4*)&s->xhi[so + 8] = *(const uint4*)(ahi + gx + 8);
            *(uint4*)&s->xlo[so]     = *(const uint4*)(alo + gx);
            *(uint4*)&s->xlo[so + 8] = *(const uint4*)(alo + gx + 8);
        }
        {
            size_t gw = (size_t)(n0 + lrow) * DMODEL + k0 + lseg;
            uint32_t so = lrow * KSTR + lseg;
            *(uint4*)&s->whi[so]     = *(const uint4*)(bhi + gw);
            *(uint4*)&s->whi[so + 8] = *(const uint4*)(bhi + gw + 8);
            *(uint4*)&s->wlo[so]     = *(const uint4*)(blo + gw);
            *(uint4*)&s->wlo[so + 8] = *(const uint4*)(blo + gw + 8);
        }
        __syncthreads();

        #pragma unroll
        for (int kk = 0; kk < 4; kk++) {
            const int kc = 16 * kk + 2 * t;
            uint32_t ah[4], al[4];
            ah[0] = *(const uint32_t*)&s->xhi[(m0 + g) * KSTR + kc];
            ah[1] = *(const uint32_t*)&s->xhi[(m0 + g + 8) * KSTR + kc];
            ah[2] = *(const uint32_t*)&s->xhi[(m0 + g) * KSTR + kc + 8];
            ah[3] = *(const uint32_t*)&s->xhi[(m0 + g + 8) * KSTR + kc + 8];
            al[0] = *(const uint32_t*)&s->xlo[(m0 + g) * KSTR + kc];
            al[1] = *(const uint32_t*)&s->xlo[(m0 + g + 8) * KSTR + kc];
            al[2] = *(const uint32_t*)&s->xlo[(m0 + g) * KSTR + kc + 8];
            al[3] = *(const uint32_t*)&s->xlo[(m0 + g + 8) * KSTR + kc + 8];
            #pragma unroll
            for (int j = 0; j < 8; j++) {
                const int n = 8 * j + g;
                uint32_t bh0 = *(const uint32_t*)&s->whi[n * KSTR + kc];
                uint32_t bh1 = *(const uint32_t*)&s->whi[n * KSTR + kc + 8];
                uint32_t bl0 = *(const uint32_t*)&s->wlo[n * KSTR + kc];
                uint32_t bl1 = *(const uint32_t*)&s->wlo[n * KSTR + kc + 8];
                mma16816(acc[j], ah, bh0, bh1);
                mma16816(acc[j], al, bh0, bh1);
                mma16816(acc[j], ah, bl0, bl1);
            }
        }
    }
}

// ---------------------------------------------------------------------------
// QKV projection via SMEM-staged HMMA + fused LayerNorm (q,k). (R10.)
// ---------------------------------------------------------------------------
__global__ __launch_bounds__(256)
void qkv_mma(const float* __restrict__ bq, const float* __restrict__ bk,
             const float* __restrict__ bv,
             const float* __restrict__ gamma, const float* __restrict__ beta)
{
    extern __shared__ char smraw[];
    ProjSmem* s = (ProjSmem*)smraw;

    const int mat  = blockIdx.y >> 3;
    const int head = blockIdx.y & 7;
    const int row0 = blockIdx.x * 128;
    const int tid = threadIdx.x;
    const int warp = tid >> 5, lane = tid & 31;
    const int g = lane >> 2, t = lane & 3;
    const int m0 = warp * 16;

    const float* bias = (mat == 0) ? bq : (mat == 1) ? bk : bv;
    float*       out  = (mat == 0) ? g_q : (mat == 1) ? g_k : g_v;
    const __nv_bfloat16* wh = gw_hi + (size_t)mat * DMODEL * DMODEL + (size_t)head * 64 * DMODEL;
    const __nv_bfloat16* wl = gw_lo + (size_t)mat * DMODEL * DMODEL + (size_t)head * 64 * DMODEL;

    float acc[8][4];
    #pragma unroll
    for (int j = 0; j < 8; j++)
        #pragma unroll
        for (int i = 0; i < 4; i++) acc[j][i] = 0.f;

    proj_tiles_mma(s, gx_hi, gx_lo, wh, wl, row0, 0, acc);

    #pragma unroll
    for (int j = 0; j < 8; j++) {
        float b0v = bias[head * 64 + 8 * j + 2 * t];
        float b1v = bias[head * 64 + 8 * j + 2 * t + 1];
        acc[j][0] += b0v; acc[j][1] += b1v;
        acc[j][2] += b0v; acc[j][3] += b1v;
    }

    if (mat < 2) {
        float s0 = 0.f, s1 = 0.f;
        #pragma unroll
        for (int j = 0; j < 8; j++) {
            s0 += acc[j][0] + acc[j][1];
            s1 += acc[j][2] + acc[j][3];
        }
        s0 += __shfl_xor_sync(~0u, s0, 1); s0 += __shfl_xor_sync(~0u, s0, 2);
        s1 += __shfl_xor_sync(~0u, s1, 1); s1 += __shfl_xor_sync(~0u, s1, 2);
        float mu0 = s0 * (1.f / 64.f), mu1 = s1 * (1.f / 64.f);
        float v0 = 0.f, v1 = 0.f;
        #pragma unroll
        for (int j = 0; j < 8; j++) {
            acc[j][0] -= mu0; acc[j][1] -= mu0;
            acc[j][2] -= mu1; acc[j][3] -= mu1;
            v0 += acc[j][0] * acc[j][0] + acc[j][1] * acc[j][1];
            v1 += acc[j][2] * acc[j][2] + acc[j][3] * acc[j][3];
        }
        v0 += __shfl_xor_sync(~0u, v0, 1); v0 += __shfl_xor_sync(~0u, v0, 2);
        v1 += __shfl_xor_sync(~0u, v1, 1); v1 += __shfl_xor_sync(~0u, v1, 2);
        float inv0 = rsqrtf(v0 * (1.f / 64.f) + 1e-5f);
        float inv1 = rsqrtf(v1 * (1.f / 64.f) + 1e-5f);
        #pragma unroll
        for (int j = 0; j < 8; j++) {
            float ga0 = gamma[8 * j + 2 * t], ga1 = gamma[8 * j + 2 * t + 1];
            float be0 = beta[8 * j + 2 * t],  be1 = beta[8 * j + 2 * t + 1];
            acc[j][0] = acc[j][0] * inv0 * ga0 + be0;
            acc[j][1] = acc[j][1] * inv0 * ga1 + be1;
            acc[j][2] = acc[j][2] * inv1 * ga0 + be0;
            acc[j][3] = acc[j][3] * inv1 * ga1 + be1;
        }
    }

    const int r0 = row0 + m0 + g, r1 = r0 + 8;
    const int b0i = r0 >> 10, ss0 = r0 & 1023;
    const int b1i = r1 >> 10, ss1 = r1 & 1023;
    float* o0 = out + (((size_t)b0i * NHEADS + head) * SEQ + ss0) * DK;
    float* o1 = out + (((size_t)b1i * NHEADS + head) * SEQ + ss1) * DK;
    #pragma unroll
    for (int j = 0; j < 8; j++) {
        *(float2*)(o0 + 8 * j + 2 * t) = make_float2(acc[j][0], acc[j][1]);
        *(float2*)(o1 + 8 * j + 2 * t) = make_float2(acc[j][2], acc[j][3]);
    }
}

// ---------------------------------------------------------------------------
// Output projection via SMEM-staged HMMA. (R10.)
// ---------------------------------------------------------------------------
__global__ __launch_bounds__(256)
void out_mma(const float* __restrict__ bo, float* __restrict__ C)
{
    extern __shared__ char smraw[];
    ProjSmem* s = (ProjSmem*)smraw;

    const int n0   = blockIdx.y * 64;
    const int row0 = blockIdx.x * 128;
    const int tid = threadIdx.x;
    const int warp = tid >> 5, lane = tid & 31;
    const int g = lane >> 2, t = lane & 3;
    const int m0 = warp * 16;

    const __nv_bfloat16* wh = gw_hi + (size_t)3 * DMODEL * DMODEL;
    const __nv_bfloat16* wl = gw_lo + (size_t)3 * DMODEL * DMODEL;

    float acc[8][4];
    #pragma unroll
    for (int j = 0; j < 8; j++)
        #pragma unroll
        for (int i = 0; i < 4; i++) acc[j][i] = 0.f;

    proj_tiles_mma(s, go_hi, go_lo, wh, wl, row0, n0, acc);

    const int r0 = row0 + m0 + g, r1 = r0 + 8;
    #pragma unroll
    for (int j = 0; j < 8; j++) {
        float b0v = bo[n0 + 8 * j + 2 * t];
        float b1v = bo[n0 + 8 * j + 2 * t + 1];
        *(float2*)(C + (size_t)r0 * DMODEL + n0 + 8 * j + 2 * t) =
            make_float2(acc[j][0] + b0v, acc[j][1] + b1v);
        *(float2*)(C + (size_t)r1 * DMODEL + n0 + 8 * j + 2 * t) =
            make_float2(acc[j][2] + b0v, acc[j][3] + b1v);
    }
}

// ---------------------------------------------------------------------------
// Prep: split K -> bf16 hi/lo (K-major), and K^T, V^T -> bf16 hi/lo (d-major).
// ---------------------------------------------------------------------------
__global__ __launch_bounds__(256)
void prep_kernel()
{
    __shared__ float ts[64][65];
    const int bh = blockIdx.y;
    const int s0 = blockIdx.x * 64;
    const int tid = threadIdx.x;

    for (int idx = tid; idx < 4096; idx += 256) {
        int r = idx >> 6, d = idx & 63;
        float x = g_k[((size_t)bh * SEQ + s0 + r) * DK + d];
        float h, l; hilo(x, h, l);
        size_t o = ((size_t)bh * SEQ + s0 + r) * DK + d;
        gk_hi[o] = __float2bfloat16(h);
        gk_lo[o] = __float2bfloat16(l);
        ts[r][d] = x;
    }
    __syncthreads();
    for (int idx = tid; idx < 4096; idx += 256) {
        int d = idx >> 6, s = idx & 63;
        float x = ts[s][d];
        float h, l; hilo(x, h, l);
        size_t o = ((size_t)bh * DK + d) * SEQ + s0 + s;
        gkt_hi[o] = __float2bfloat16(h);
        gkt_lo[o] = __float2bfloat16(l);
    }
    __syncthreads();
    for (int idx = tid; idx < 4096; idx += 256) {
        int r = idx >> 6, d = idx & 63;
        ts[r][d] = g_v[((size_t)bh * SEQ + s0 + r) * DK + d];
    }
    __syncthreads();
    for (int idx = tid; idx < 4096; idx += 256) {
        int d = idx >> 6, s = idx & 63;
        float x = ts[s][d];
        float h, l; hilo(x, h, l);
        size_t o = ((size_t)bh * DK + d) * SEQ + s0 + s;
        gvt_hi[o] = __float2bfloat16(h);
        gvt_lo[o] = __float2bfloat16(l);
    }
}

// ---------------------------------------------------------------------------
// Attention (R11 design — best passing): mma.sync + cp.async double-buffered
// tiles + truncation split-pack. Buffer ping-pong eps gate via g_cur.
// O = softmax(Q K^T / 8) @ Vals, Vals = K (pass 0-2, accumulating ssq) or V.
// grid = (SEQ/128, BHD), 256 threads, dyn smem 73728 B.
// ---------------------------------------------------------------------------
#define TILE_B   9216          // one region: 64*KSTR*2 bytes
#define BUF_B    (4*TILE_B)    // khi,klo,vhi,vlo
#define ATTN_SMEM (2*BUF_B)    // 73728

__global__ __launch_bounds__(256)
void attn_mma(int finalPass)
{
    extern __shared__ char smraw[];
    const uint32_t sbase = smem_addr_u32(smraw);

    const int tid  = threadIdx.x;
    const int warp = tid >> 5;
    const int lane = tid & 31;
    const int g = lane >> 2;
    const int t = lane & 3;
    const int bh = blockIdx.y;
    const int q0 = blockIdx.x * 128;
    const int m0 = warp * 16;

    const int cur = g_cur;
    const float* qsrc = cur ? g_nq : g_q;
    float*       qdst = cur ? g_q : g_nq;
    const float* qb = qsrc + ((size_t)bh * SEQ + q0) * DK;

    // ---- Q fragments (hi/lo) via truncation split ----
    uint32_t qh[4][4], ql[4][4];
    {
        const float* r0p = qb + (size_t)(m0 + g) * DK;
        const float* r1p = qb + (size_t)(m0 + g + 8) * DK;
        #pragma unroll
        for (int kt = 0; kt < 4; kt++) {
            float2 v00 = *(const float2*)(r0p + 16 * kt + 2 * t);
            float2 v10 = *(const float2*)(r1p + 16 * kt + 2 * t);
            float2 v01 = *(const float2*)(r0p + 16 * kt + 2 * t + 8);
            float2 v11 = *(const float2*)(r1p + 16 * kt + 2 * t + 8);
            split2(v00.x, v00.y, qh[kt][0], ql[kt][0]);
            split2(v10.x, v10.y, qh[kt][1], ql[kt][1]);
            split2(v01.x, v01.y, qh[kt][2], ql[kt][2]);
            split2(v11.x, v11.y, qh[kt][3], ql[kt][3]);
        }
    }

    float oc[8][4];
    #pragma unroll
    for (int j = 0; j < 8; j++)
        #pragma unroll
        for (int i = 0; i < 4; i++) oc[j][i] = 0.f;
    float lac0 = 0.f, lac1 = 0.f;

    const __nv_bfloat16* pkhi = gk_hi + (size_t)bh * SEQ * DK;
    const __nv_bfloat16* pklo = gk_lo + (size_t)bh * SEQ * DK;
    const __nv_bfloat16* pbhi = (finalPass ? gvt_hi : gkt_hi) + (size_t)bh * DK * SEQ;
    const __nv_bfloat16* pblo = (finalPass ? gvt_lo : gkt_lo) + (size_t)bh * DK * SEQ;

    const int lrow = tid >> 2;             // 0..63
    const int lseg = (tid & 3) * 16;       // bf16 col offset (0,16,32,48)
    const uint32_t soB = (uint32_t)(lrow * KSTR + lseg) * 2;   // byte offset

    auto issue_tile = [&](int kt64, int buf) {
        uint32_t b = sbase + buf * BUF_B + soB;
        size_t gk = ((size_t)(kt64 * 64 + lrow)) * DK + lseg;
        size_t gb = (size_t)lrow * SEQ + kt64 * 64 + lseg;
        CPA16(b,                     pkhi + gk);
        CPA16(b + 16,                pkhi + gk + 8);
        CPA16(b + TILE_B,            pklo + gk);
        CPA16(b + TILE_B + 16,       pklo + gk + 8);
        CPA16(b + 2 * TILE_B,        pbhi + gb);
        CPA16(b + 2 * TILE_B + 16,   pbhi + gb + 8);
        CPA16(b + 3 * TILE_B,        pblo + gb);
        CPA16(b + 3 * TILE_B + 16,   pblo + gb + 8);
    };

    issue_tile(0, 0);
    CPA_COMMIT();

    for (int kt64 = 0; kt64 < SEQ / 64; kt64++) {
        const int curbuf = kt64 & 1;
        if (kt64 + 1 < SEQ / 64) {
            issue_tile(kt64 + 1, curbuf ^ 1);
            CPA_COMMIT();
            CPA_WAIT1();
        } else {
            CPA_WAIT0();
        }
        __syncthreads();

        const __nv_bfloat16* s_khi = (const __nv_bfloat16*)(smraw + curbuf * BUF_B);
        const __nv_bfloat16* s_klo = (const __nv_bfloat16*)(smraw + curbuf * BUF_B + TILE_B);
        const __nv_bfloat16* s_vhi = (const __nv_bfloat16*)(smraw + curbuf * BUF_B + 2 * TILE_B);
        const __nv_bfloat16* s_vlo = (const __nv_bfloat16*)(smraw + curbuf * BUF_B + 3 * TILE_B);

        // ---- S = Q K^T ----
        float sc[8][4];
        #pragma unroll
        for (int j = 0; j < 8; j++)
            #pragma unroll
            for (int i = 0; i < 4; i++) sc[j][i] = 0.f;

        #pragma unroll
        for (int j = 0; j < 8; j++) {
            int key = 8 * j + g;
            #pragma unroll
            for (int kk = 0; kk < 4; kk++) {
                int kc = 16 * kk + 2 * t;
                uint32_t bh0 = *(const uint32_t*)&s_khi[key * KSTR + kc];
                uint32_t bh1 = *(const uint32_t*)&s_khi[key * KSTR + kc + 8];
                uint32_t bl0 = *(const uint32_t*)&s_klo[key * KSTR + kc];
                uint32_t bl1 = *(const uint32_t*)&s_klo[key * KSTR + kc + 8];
                mma16816(sc[j], qh[kk], bh0, bh1);
                mma16816(sc[j], ql[kk], bh0, bh1);
                mma16816(sc[j], qh[kk], bl0, bl1);
            }
        }

        // ---- softmax (fixed max 8) + truncation split-pack into A-frags ----
        uint32_t pah[4][4], pal[4][4];
        #pragma unroll
        for (int kk = 0; kk < 4; kk++) {
            float e0a = __expf(fmaf(sc[2*kk][0],   0.125f, -8.f));
            float e0b = __expf(fmaf(sc[2*kk][1],   0.125f, -8.f));
            float e0c = __expf(fmaf(sc[2*kk][2],   0.125f, -8.f));
            float e0d = __expf(fmaf(sc[2*kk][3],   0.125f, -8.f));
            float e1a = __expf(fmaf(sc[2*kk+1][0], 0.125f, -8.f));
            float e1b = __expf(fmaf(sc[2*kk+1][1], 0.125f, -8.f));
            float e1c = __expf(fmaf(sc[2*kk+1][2], 0.125f, -8.f));
            float e1d = __expf(fmaf(sc[2*kk+1][3], 0.125f, -8.f));
            lac0 += e0a + e0b + e1a + e1b;
            lac1 += e0c + e0d + e1c + e1d;
            split2(e0a, e0b, pah[kk][0], pal[kk][0]);
            split2(e0c, e0d, pah[kk][1], pal[kk][1]);
            split2(e1a, e1b, pah[kk][2], pal[kk][2]);
            split2(e1c, e1d, pah[kk][3], pal[kk][3]);
        }

        // ---- O += P @ Vals ----
        #pragma unroll
        for (int j = 0; j < 8; j++) {
            int dd = 8 * j + g;
            #pragma unroll
            for (int kk = 0; kk < 4; kk++) {
                int kc = 16 * kk + 2 * t;
                uint32_t vh0 = *(const uint32_t*)&s_vhi[dd * KSTR + kc];
                uint32_t vh1 = *(const uint32_t*)&s_vhi[dd * KSTR + kc + 8];
                uint32_t vl0 = *(const uint32_t*)&s_vlo[dd * KSTR + kc];
                uint32_t vl1 = *(const uint32_t*)&s_vlo[dd * KSTR + kc + 8];
                mma16816(oc[j], pah[kk], vh0, vh1);
                mma16816(oc[j], pal[kk], vh0, vh1);
                mma16816(oc[j], pah[kk], vl0, vl1);
            }
        }
        __syncthreads();   // all reads done before this buffer is refilled
    }

    // ---- epilogue: normalize, store, ssq ----
    lac0 += __shfl_xor_sync(~0u, lac0, 1);
    lac0 += __shfl_xor_sync(~0u, lac0, 2);
    lac1 += __shfl_xor_sync(~0u, lac1, 1);
    lac1 += __shfl_xor_sync(~0u, lac1, 2);
    const float inv0 = 1.0f / lac0;
    const float inv1 = 1.0f / lac1;

    float* ob0 = qdst + ((size_t)bh * SEQ + q0 + m0 + g) * DK;
    float* ob1 = qdst + ((size_t)bh * SEQ + q0 + m0 + g + 8) * DK;
    const float* qr0 = qb + (size_t)(m0 + g) * DK;
    const float* qr1 = qb + (size_t)(m0 + g + 8) * DK;
    float local = 0.f;
    #pragma unroll
    for (int j = 0; j < 8; j++) {
        int c = 8 * j + 2 * t;
        float2 w0 = make_float2(oc[j][0] * inv0, oc[j][1] * inv0);
        float2 w1 = make_float2(oc[j][2] * inv1, oc[j][3] * inv1);
        *(float2*)(ob0 + c) = w0;
        *(float2*)(ob1 + c) = w1;
        if (!finalPass) {
            float2 a = *(const float2*)(qr0 + c);
            float2 b = *(const float2*)(qr1 + c);
            float d0 = w0.x - a.x, d1 = w0.y - a.y;
            float d2 = w1.x - b.x, d3 = w1.y - b.y;
            local += d0 * d0 + d1 * d1 + d2 * d2 + d3 * d3;
        }
    }
    if (!finalPass) {
        #pragma unroll
        for (int off = 16; off; off >>= 1)
            local += __shfl_xor_sync(~0u, local, off);
        if (lane == 0) atomicAdd(&g_ssq, local);
    }
}

// ---------------------------------------------------------------------------
__global__ void init_state_kernel() { g_cur = 0; g_ssq = 0.0f; }

// eps gate: flip current-q buffer iff ||new_q - q|| > 1e-4; reset ssq.
__global__ void gate_flip_kernel()
{
    if (g_ssq > 1e-8f) g_cur ^= 1;
    g_ssq = 0.0f;
}

// ---------------------------------------------------------------------------
// prep_o: gather final attn output -> go hi/lo [token][512] row-major.
// Final O lives in the buffer OPPOSITE to g_cur (attn always writes !g_cur).
// ---------------------------------------------------------------------------
__global__ __launch_bounds__(256)
void prep_o()
{
    const float* src = g_cur ? g_q : g_nq;
    int i4 = blockIdx.x * 256 + threadIdx.x;
    int dq = (i4 & 15) * 4;
    int tk = i4 >> 4;
    float4 v = *(const float4*)(src + (size_t)tk * DK + dq);
    int bh = tk >> 10, s = tk & 1023;
    int b = bh >> 3, h = bh & 7;
    size_t o = ((size_t)(b * SEQ + s)) * DMODEL + h * 64 + dq;
    uint32_t h01, l01, h23, l23;
    split2(v.x, v.y, h01, l01);
    split2(v.z, v.w, h23, l23);
    *(uint32_t*)&go_hi[o]     = h01;
    *(uint32_t*)&go_hi[o + 2] = h23;
    *(uint32_t*)&go_lo[o]     = l01;
    *(uint32_t*)&go_lo[o + 2] = l23;
}

// ---------------------------------------------------------------------------
extern "C" void kernel_launch(void* const* d_in, const int* in_sizes, int n_in,
                              void* d_out, int out_size)
{
    const float* x     = (const float*)d_in[0];
    const float* Wq    = (const float*)d_in[1];
    const float* bq    = (const float*)d_in[2];
    const float* Wk    = (const float*)d_in[3];
    const float* bk    = (const float*)d_in[4];
    const float* Wv    = (const float*)d_in[5];
    const float* bv    = (const float*)d_in[6];
    const float* Wo    = (const float*)d_in[7];
    const float* bo    = (const float*)d_in[8];
    const float* gamma = (const float*)d_in[9];
    const float* beta  = (const float*)d_in[10];
    float* out = (float*)d_out;

    const int projSmem = (int)sizeof(ProjSmem);   // 55296 B
    cudaFuncSetAttribute(qkv_mma,
                         cudaFuncAttributeMaxDynamicSharedMemorySize, projSmem);
    cudaFuncSetAttribute(out_mma,
                         cudaFuncAttributeMaxDynamicSharedMemorySize, projSmem);
    cudaFuncSetAttribute(attn_mma,
                         cudaFuncAttributeMaxDynamicSharedMemorySize, ATTN_SMEM);

    // 0. state init + hi/lo splits of x and W^T
    init_state_kernel<<<1, 1>>>();
    prep_x<<<XW_ELEMS / 4 / 256, 256>>>(x);
    prep_w<<<dim3(8, 8, 4), 256>>>(Wq, Wk, Wv, Wo);
    // 1. QKV projections via SMEM-staged HMMA (+ fused LayerNorm for q,k)
    qkv_mma<<<dim3(TOKENS / 128, 24), 256, projSmem>>>(bq, bk, bv, gamma, beta);
    // 2. bf16 hi/lo splits of K, K^T, V^T
    prep_kernel<<<dim3(SEQ / 64, BHD), 256>>>();
    // 3. Hopfield update iterations (values = K), buffer ping-pong eps gate
    for (int it = 0; it < 3; it++) {
        attn_mma<<<dim3(SEQ / 128, BHD), 256, ATTN_SMEM>>>(0);
        gate_flip_kernel<<<1, 1>>>();
    }
    // 4. Final retrieval (values = V)
    attn_mma<<<dim3(SEQ / 128, BHD), 256, ATTN_SMEM>>>(1);
    // 5. Output projection via SMEM-staged HMMA
    prep_o<<<XW_ELEMS / 4 / 256, 256>>>();
    out_mma<<<dim3(TOKENS / 128, 8), 256, projSmem>>>(bo, out);
}

// round 15
// speedup vs baseline: 1.2091x; 1.0205x over previous
#include <cuda_runtime.h>
#include <cuda_bf16.h>
#include <cstdint>

#define NHEADS   8
#define DK       64
#define SEQ      1024
#define BATCH    8
#define DMODEL   512
#define BHD      (BATCH*NHEADS)          // 64
#define TOKENS   (BATCH*SEQ)             // 8192
#define QKV_ELEMS (BHD*SEQ*DK)           // 4194304
#define XW_ELEMS (TOKENS*DMODEL)         // 4194304

// ---------------- scratch (device globals; no allocation allowed) ----------
__device__ float g_q[QKV_ELEMS];
__device__ float g_k[QKV_ELEMS];
__device__ float g_v[QKV_ELEMS];
__device__ float g_nq[QKV_ELEMS];
__device__ float g_ssq;
__device__ int   g_cur;                  // 0: current q in g_q, 1: in g_nq

// bf16 hi/lo splits (built per launch)
__device__ __align__(256) __nv_bfloat16 gk_hi[QKV_ELEMS];   // K, K-major
__device__ __align__(256) __nv_bfloat16 gk_lo[QKV_ELEMS];
__device__ __align__(256) __nv_bfloat16 gkt_hi[QKV_ELEMS];  // K^T, d-major
__device__ __align__(256) __nv_bfloat16 gkt_lo[QKV_ELEMS];
__device__ __align__(256) __nv_bfloat16 gvt_hi[QKV_ELEMS];  // V^T, d-major
__device__ __align__(256) __nv_bfloat16 gvt_lo[QKV_ELEMS];
__device__ __align__(256) __nv_bfloat16 gx_hi[XW_ELEMS];    // x, row-major
__device__ __align__(256) __nv_bfloat16 gx_lo[XW_ELEMS];
__device__ __align__(256) __nv_bfloat16 gw_hi[4*DMODEL*DMODEL]; // W^T [n][k]
__device__ __align__(256) __nv_bfloat16 gw_lo[4*DMODEL*DMODEL];
__device__ __align__(256) __nv_bfloat16 go_hi[XW_ELEMS];    // attn out gathered
__device__ __align__(256) __nv_bfloat16 go_lo[XW_ELEMS];

// ---------------- helpers ----------------------------------------------------
__device__ __forceinline__ void hilo(float x, float& h, float& l) {
    h = __bfloat162float(__float2bfloat16(x));
    l = x - h;
}
// Truncation split of a pair: hp = {bf16_trunc(a), bf16_trunc(b)} via PRMT,
// lp = {bf16_rn(a-hi_a), bf16_rn(b-hi_b)} via one cvt.rn.bf16x2.
__device__ __forceinline__ void split2(float a, float b,
                                       uint32_t& hp, uint32_t& lp) {
    uint32_t ua = __float_as_uint(a), ub = __float_as_uint(b);
    float ha = __uint_as_float(ua & 0xFFFF0000u);
    float hb = __uint_as_float(ub & 0xFFFF0000u);
    asm("prmt.b32 %0, %1, %2, 0x7632;" : "=r"(hp) : "r"(ua), "r"(ub));
    float la = a - ha, lb = b - hb;
    asm("cvt.rn.bf16x2.f32 %0, %1, %2;" : "=r"(lp) : "f"(lb), "f"(la));
}
// m16n8k16 bf16 MMA, f32 accumulate (sm_80 baseline PTX -> HMMA on sm_103a)
__device__ __forceinline__ void mma16816(float c[4], const uint32_t a[4],
                                         uint32_t b0, uint32_t b1) {
    asm volatile(
        "mma.sync.aligned.m16n8k16.row.col.f32.bf16.bf16.f32 "
        "{%0,%1,%2,%3}, {%4,%5,%6,%7}, {%8,%9}, {%0,%1,%2,%3};"
        : "+f"(c[0]), "+f"(c[1]), "+f"(c[2]), "+f"(c[3])
        : "r"(a[0]), "r"(a[1]), "r"(a[2]), "r"(a[3]), "r"(b0), "r"(b1));
}
// cp.async 16B (sm_80 baseline)
#define CPA16(dst_u32, src_ptr) \
    asm volatile("cp.async.cg.shared.global [%0], [%1], 16;" \
                 :: "r"(dst_u32), "l"(src_ptr))
#define CPA_COMMIT() asm volatile("cp.async.commit_group;" ::: "memory")
#define CPA_WAIT1()  asm volatile("cp.async.wait_group 1;" ::: "memory")
#define CPA_WAIT0()  asm volatile("cp.async.wait_group 0;" ::: "memory")

__device__ __forceinline__ uint32_t smem_addr_u32(const void* p) {
    uint32_t a;
    asm("{ .reg .u64 t; cvta.to.shared.u64 t, %1; cvt.u32.u64 %0, t; }"
        : "=r"(a) : "l"(p));
    return a;
}

#define KSTR 72   // smem row stride in bf16 (144 B) -> conflict-free fragments

// ---------------------------------------------------------------------------
// prep_x: split x into bf16 hi/lo (row-major).
// ---------------------------------------------------------------------------
__global__ __launch_bounds__(256)
void prep_x(const float* __restrict__ x)
{
    int i = (blockIdx.x * 256 + threadIdx.x) * 4;
    float4 v = *(const float4*)(x + i);
    uint32_t h01, l01, h23, l23;
    split2(v.x, v.y, h01, l01);
    split2(v.z, v.w, h23, l23);
    *(uint32_t*)&gx_hi[i]     = h01;
    *(uint32_t*)&gx_hi[i + 2] = h23;
    *(uint32_t*)&gx_lo[i]     = l01;
    *(uint32_t*)&gx_lo[i + 2] = l23;
}

// ---------------------------------------------------------------------------
// prep_w: transpose each W (k-major 512x512) into [n][k] and split hi/lo.
// ---------------------------------------------------------------------------
__global__ __launch_bounds__(256)
void prep_w(const float* __restrict__ Wq, const float* __restrict__ Wk,
            const float* __restrict__ Wv, const float* __restrict__ Wo)
{
    __shared__ float tile[64][65];
    const int z = blockIdx.z;
    const float* W = (z == 0) ? Wq : (z == 1) ? Wk : (z == 2) ? Wv : Wo;
    const int k0 = blockIdx.x * 64, n0 = blockIdx.y * 64;
    const int tid = threadIdx.x;

    for (int idx = tid; idx < 4096; idx += 256) {
        int r = idx >> 6, c = idx & 63;
        tile[r][c] = W[(size_t)(k0 + r) * DMODEL + n0 + c];
    }
    __syncthreads();
    for (int idx = tid * 2; idx < 4096; idx += 512) {
        int r = idx >> 6, c = idx & 63;           // r: n-local, c: k-local
        uint32_t hp, lp;
        split2(tile[c][r], tile[c + 1][r], hp, lp);
        size_t o = (size_t)z * DMODEL * DMODEL + (size_t)(n0 + r) * DMODEL + k0 + c;
        *(uint32_t*)&gw_hi[o] = hp;
        *(uint32_t*)&gw_lo[o] = lp;
    }
}

// ---------------------------------------------------------------------------
// Wide (N=128) SMEM-staged HMMA projection body: C[128 x 128] tile.
// A: [128 x 512] row-major hi/lo; B^T: 128 n-rows x 512 k, [n][k] hi/lo.
// 256 threads / 8 warps; warp owns 16 rows x all 128 cols; acc[16][4].
// ---------------------------------------------------------------------------
struct Proj2Smem {
    __nv_bfloat16 xhi[128 * KSTR];
    __nv_bfloat16 xlo[128 * KSTR];
    __nv_bfloat16 whi[128 * KSTR];
    __nv_bfloat16 wlo[128 * KSTR];
};

__device__ __forceinline__ void proj2_tiles_mma(
    Proj2Smem* s,
    const __nv_bfloat16* __restrict__ ahi, const __nv_bfloat16* __restrict__ alo,
    const __nv_bfloat16* __restrict__ bhi, const __nv_bfloat16* __restrict__ blo,
    int row0, float acc[16][4])
{
    const int tid = threadIdx.x;
    const int warp = tid >> 5, lane = tid & 31;
    const int g = lane >> 2, t = lane & 3;
    const int m0 = warp * 16;
    const int lrow = tid >> 2, lseg = (tid & 3) * 16;

    for (int kt = 0; kt < DMODEL / 64; kt++) {
        const int k0 = kt * 64;
        __syncthreads();
        #pragma unroll
        for (int half = 0; half < 2; half++) {
            int xr = half * 64 + lrow;
            size_t gx = (size_t)(row0 + xr) * DMODEL + k0 + lseg;
            uint32_t so = xr * KSTR + lseg;
            *(uint4*)&s->xhi[so]     = *(const uint4*)(ahi + gx);
            *(uint4*)&s->xhi[so + 8] = *(const uint4*)(ahi + gx + 8);
            *(uint4*)&s->xlo[so]     = *(const uint4*)(alo + gx);
            *(uint4*)&s->xlo[so + 8] = *(const uint4*)(alo + gx + 8);
            size_t gw = (size_t)xr * DMODEL + k0 + lseg;   // n-row xr of B
            *(uint4*)&s->whi[so]     = *(const uint4*)(bhi + gw);
            *(uint4*)&s->whi[so + 8] = *(const uint4*)(bhi + gw + 8);
            *(uint4*)&s->wlo[so]     = *(const uint4*)(blo + gw);
            *(uint4*)&s->wlo[so + 8] = *(const uint4*)(blo + gw + 8);
        }
        __syncthreads();

        #pragma unroll
        for (int kk = 0; kk < 4; kk++) {
            const int kc = 16 * kk + 2 * t;
            uint32_t ah[4], al[4];
            ah[0] = *(const uint32_t*)&s->xhi[(m0 + g) * KSTR + kc];
            ah[1] = *(const uint32_t*)&s->xhi[(m0 + g + 8) * KSTR + kc];
            ah[2] = *(const uint32_t*)&s->xhi[(m0 + g) * KSTR + kc + 8];
            ah[3] = *(const uint32_t*)&s->xhi[(m0 + g + 8) * KSTR + kc + 8];
            al[0] = *(const uint32_t*)&s->xlo[(m0 + g) * KSTR + kc];
            al[1] = *(const uint32_t*)&s->xlo[(m0 + g + 8) * KSTR + kc];
            al[2] = *(const uint32_t*)&s->xlo[(m0 + g) * KSTR + kc + 8];
            al[3] = *(const uint32_t*)&s->xlo[(m0 + g + 8) * KSTR + kc + 8];
            #pragma unroll
            for (int j = 0; j < 16; j++) {
                const int n = 8 * j + g;
                uint32_t bh0 = *(const uint32_t*)&s->whi[n * KSTR + kc];
                uint32_t bh1 = *(const uint32_t*)&s->whi[n * KSTR + kc + 8];
                uint32_t bl0 = *(const uint32_t*)&s->wlo[n * KSTR + kc];
                uint32_t bl1 = *(const uint32_t*)&s->wlo[n * KSTR + kc + 8];
                mma16816(acc[j], ah, bh0, bh1);
                mma16816(acc[j], al, bh0, bh1);
                mma16816(acc[j], ah, bl0, bl1);
            }
        }
    }
}

// ---------------------------------------------------------------------------
// QKV projection, N=128 (two heads per block) + fused per-head LayerNorm.
// grid = (TOKENS/128, 12): blockIdx.y = mat*4 + headpair.
// ---------------------------------------------------------------------------
__global__ __launch_bounds__(256)
void qkv_mma(const float* __restrict__ bq, const float* __restrict__ bk,
             const float* __restrict__ bv,
             const float* __restrict__ gamma, const float* __restrict__ beta)
{
    extern __shared__ char smraw[];
    Proj2Smem* s = (Proj2Smem*)smraw;

    const int mat   = blockIdx.y >> 2;
    const int head0 = (blockIdx.y & 3) * 2;
    const int row0  = blockIdx.x * 128;
    const int tid = threadIdx.x;
    const int warp = tid >> 5, lane = tid & 31;
    const int g = lane >> 2, t = lane & 3;
    const int m0 = warp * 16;

    const float* bias = (mat == 0) ? bq : (mat == 1) ? bk : bv;
    float*       out  = (mat == 0) ? g_q : (mat == 1) ? g_k : g_v;
    const __nv_bfloat16* wh = gw_hi + (size_t)mat * DMODEL * DMODEL
                            + (size_t)head0 * 64 * DMODEL;
    const __nv_bfloat16* wl = gw_lo + (size_t)mat * DMODEL * DMODEL
                            + (size_t)head0 * 64 * DMODEL;

    float acc[16][4];
    #pragma unroll
    for (int j = 0; j < 16; j++)
        #pragma unroll
        for (int i = 0; i < 4; i++) acc[j][i] = 0.f;

    proj2_tiles_mma(s, gx_hi, gx_lo, wh, wl, row0, acc);

    // bias (per head: j 0..7 -> head0, j 8..15 -> head0+1)
    #pragma unroll
    for (int j = 0; j < 16; j++) {
        int head = head0 + (j >> 3);
        int col = (j & 7) * 8 + 2 * t;
        float b0v = bias[head * 64 + col];
        float b1v = bias[head * 64 + col + 1];
        acc[j][0] += b0v; acc[j][1] += b1v;
        acc[j][2] += b0v; acc[j][3] += b1v;
    }

    if (mat < 2) {
        #pragma unroll
        for (int h = 0; h < 2; h++) {
            const int jb = h * 8;
            float s0 = 0.f, s1 = 0.f;
            #pragma unroll
            for (int jj = 0; jj < 8; jj++) {
                s0 += acc[jb + jj][0] + acc[jb + jj][1];
                s1 += acc[jb + jj][2] + acc[jb + jj][3];
            }
            s0 += __shfl_xor_sync(~0u, s0, 1); s0 += __shfl_xor_sync(~0u, s0, 2);
            s1 += __shfl_xor_sync(~0u, s1, 1); s1 += __shfl_xor_sync(~0u, s1, 2);
            float mu0 = s0 * (1.f / 64.f), mu1 = s1 * (1.f / 64.f);
            float v0 = 0.f, v1 = 0.f;
            #pragma unroll
            for (int jj = 0; jj < 8; jj++) {
                acc[jb + jj][0] -= mu0; acc[jb + jj][1] -= mu0;
                acc[jb + jj][2] -= mu1; acc[jb + jj][3] -= mu1;
                v0 += acc[jb + jj][0] * acc[jb + jj][0]
                    + acc[jb + jj][1] * acc[jb + jj][1];
                v1 += acc[jb + jj][2] * acc[jb + jj][2]
                    + acc[jb + jj][3] * acc[jb + jj][3];
            }
            v0 += __shfl_xor_sync(~0u, v0, 1); v0 += __shfl_xor_sync(~0u, v0, 2);
            v1 += __shfl_xor_sync(~0u, v1, 1); v1 += __shfl_xor_sync(~0u, v1, 2);
            float inv0 = rsqrtf(v0 * (1.f / 64.f) + 1e-5f);
            float inv1 = rsqrtf(v1 * (1.f / 64.f) + 1e-5f);
            #pragma unroll
            for (int jj = 0; jj < 8; jj++) {
                int col = jj * 8 + 2 * t;
                float ga0 = gamma[col], ga1 = gamma[col + 1];
                float be0 = beta[col],  be1 = beta[col + 1];
                acc[jb + jj][0] = acc[jb + jj][0] * inv0 * ga0 + be0;
                acc[jb + jj][1] = acc[jb + jj][1] * inv0 * ga1 + be1;
                acc[jb + jj][2] = acc[jb + jj][2] * inv1 * ga0 + be0;
                acc[jb + jj][3] = acc[jb + jj][3] * inv1 * ga1 + be1;
            }
        }
    }

    const int r0 = row0 + m0 + g, r1 = r0 + 8;
    const int b0i = r0 >> 10, ss0 = r0 & 1023;
    const int b1i = r1 >> 10, ss1 = r1 & 1023;
    #pragma unroll
    for (int h = 0; h < 2; h++) {
        int head = head0 + h;
        float* o0 = out + (((size_t)b0i * NHEADS + head) * SEQ + ss0) * DK;
        float* o1 = out + (((size_t)b1i * NHEADS + head) * SEQ + ss1) * DK;
        #pragma unroll
        for (int jj = 0; jj < 8; jj++) {
            int j = h * 8 + jj;
            *(float2*)(o0 + jj * 8 + 2 * t) = make_float2(acc[j][0], acc[j][1]);
            *(float2*)(o1 + jj * 8 + 2 * t) = make_float2(acc[j][2], acc[j][3]);
        }
    }
}

// ---------------------------------------------------------------------------
// Output projection, N=128. grid = (TOKENS/128, DMODEL/128).
// ---------------------------------------------------------------------------
__global__ __launch_bounds__(256)
void out_mma(const float* __restrict__ bo, float* __restrict__ C)
{
    extern __shared__ char smraw[];
    Proj2Smem* s = (Proj2Smem*)smraw;

    const int n0   = blockIdx.y * 128;
    const int row0 = blockIdx.x * 128;
    const int tid = threadIdx.x;
    const int warp = tid >> 5, lane = tid & 31;
    const int g = lane >> 2, t = lane & 3;
    const int m0 = warp * 16;

    const __nv_bfloat16* wh = gw_hi + (size_t)3 * DMODEL * DMODEL
                            + (size_t)n0 * DMODEL;
    const __nv_bfloat16* wl = gw_lo + (size_t)3 * DMODEL * DMODEL
                            + (size_t)n0 * DMODEL;

    float acc[16][4];
    #pragma unroll
    for (int j = 0; j < 16; j++)
        #pragma unroll
        for (int i = 0; i < 4; i++) acc[j][i] = 0.f;

    proj2_tiles_mma(s, go_hi, go_lo, wh, wl, row0, acc);

    const int r0 = row0 + m0 + g, r1 = r0 + 8;
    #pragma unroll
    for (int j = 0; j < 16; j++) {
        int c = n0 + 8 * j + 2 * t;
        float b0v = bo[c], b1v = bo[c + 1];
        *(float2*)(C + (size_t)r0 * DMODEL + c) =
            make_float2(acc[j][0] + b0v, acc[j][1] + b1v);
        *(float2*)(C + (size_t)r1 * DMODEL + c) =
            make_float2(acc[j][2] + b0v, acc[j][3] + b1v);
    }
}

// ---------------------------------------------------------------------------
// Prep: split K -> bf16 hi/lo (K-major), and K^T, V^T -> bf16 hi/lo (d-major).
// ---------------------------------------------------------------------------
__global__ __launch_bounds__(256)
void prep_kernel()
{
    __shared__ float ts[64][65];
    const int bh = blockIdx.y;
    const int s0 = blockIdx.x * 64;
    const int tid = threadIdx.x;

    for (int idx = tid; idx < 4096; idx += 256) {
        int r = idx >> 6, d = idx & 63;
        float x = g_k[((size_t)bh * SEQ + s0 + r) * DK + d];
        float h, l; hilo(x, h, l);
        size_t o = ((size_t)bh * SEQ + s0 + r) * DK + d;
        gk_hi[o] = __float2bfloat16(h);
        gk_lo[o] = __float2bfloat16(l);
        ts[r][d] = x;
    }
    __syncthreads();
    for (int idx = tid; idx < 4096; idx += 256) {
        int d = idx >> 6, s = idx & 63;
        float x = ts[s][d];
        float h, l; hilo(x, h, l);
        size_t o = ((size_t)bh * DK + d) * SEQ + s0 + s;
        gkt_hi[o] = __float2bfloat16(h);
        gkt_lo[o] = __float2bfloat16(l);
    }
    __syncthreads();
    for (int idx = tid; idx < 4096; idx += 256) {
        int r = idx >> 6, d = idx & 63;
        ts[r][d] = g_v[((size_t)bh * SEQ + s0 + r) * DK + d];
    }
    __syncthreads();
    for (int idx = tid; idx < 4096; idx += 256) {
        int d = idx >> 6, s = idx & 63;
        float x = ts[s][d];
        float h, l; hilo(x, h, l);
        size_t o = ((size_t)bh * DK + d) * SEQ + s0 + s;
        gvt_hi[o] = __float2bfloat16(h);
        gvt_lo[o] = __float2bfloat16(l);
    }
}

// ---------------------------------------------------------------------------
// Attention (R11 design — best passing): mma.sync + cp.async double-buffered
// tiles + truncation split-pack. Buffer ping-pong eps gate via g_cur.
// O = softmax(Q K^T / 8) @ Vals, Vals = K (pass 0-2, accumulating ssq) or V.
// grid = (SEQ/128, BHD), 256 threads, dyn smem 73728 B.
// ---------------------------------------------------------------------------
#define TILE_B   9216          // one region: 64*KSTR*2 bytes
#define BUF_B    (4*TILE_B)    // khi,klo,vhi,vlo
#define ATTN_SMEM (2*BUF_B)    // 73728

__global__ __launch_bounds__(256)
void attn_mma(int finalPass)
{
    extern __shared__ char smraw[];
    const uint32_t sbase = smem_addr_u32(smraw);

    const int tid  = threadIdx.x;
    const int warp = tid >> 5;
    const int lane = tid & 31;
    const int g = lane >> 2;
    const int t = lane & 3;
    const int bh = blockIdx.y;
    const int q0 = blockIdx.x * 128;
    const int m0 = warp * 16;

    const int cur = g_cur;
    const float* qsrc = cur ? g_nq : g_q;
    float*       qdst = cur ? g_q : g_nq;
    const float* qb = qsrc + ((size_t)bh * SEQ + q0) * DK;

    // ---- Q fragments (hi/lo) via truncation split ----
    uint32_t qh[4][4], ql[4][4];
    {
        const float* r0p = qb + (size_t)(m0 + g) * DK;
        const float* r1p = qb + (size_t)(m0 + g + 8) * DK;
        #pragma unroll
        for (int kt = 0; kt < 4; kt++) {
            float2 v00 = *(const float2*)(r0p + 16 * kt + 2 * t);
            float2 v10 = *(const float2*)(r1p + 16 * kt + 2 * t);
            float2 v01 = *(const float2*)(r0p + 16 * kt + 2 * t + 8);
            float2 v11 = *(const float2*)(r1p + 16 * kt + 2 * t + 8);
            split2(v00.x, v00.y, qh[kt][0], ql[kt][0]);
            split2(v10.x, v10.y, qh[kt][1], ql[kt][1]);
            split2(v01.x, v01.y, qh[kt][2], ql[kt][2]);
            split2(v11.x, v11.y, qh[kt][3], ql[kt][3]);
        }
    }

    float oc[8][4];
    #pragma unroll
    for (int j = 0; j < 8; j++)
        #pragma unroll
        for (int i = 0; i < 4; i++) oc[j][i] = 0.f;
    float lac0 = 0.f, lac1 = 0.f;

    const __nv_bfloat16* pkhi = gk_hi + (size_t)bh * SEQ * DK;
    const __nv_bfloat16* pklo = gk_lo + (size_t)bh * SEQ * DK;
    const __nv_bfloat16* pbhi = (finalPass ? gvt_hi : gkt_hi) + (size_t)bh * DK * SEQ;
    const __nv_bfloat16* pblo = (finalPass ? gvt_lo : gkt_lo) + (size_t)bh * DK * SEQ;

    const int lrow = tid >> 2;             // 0..63
    const int lseg = (tid & 3) * 16;       // bf16 col offset (0,16,32,48)
    const uint32_t soB = (uint32_t)(lrow * KSTR + lseg) * 2;   // byte offset

    auto issue_tile = [&](int kt64, int buf) {
        uint32_t b = sbase + buf * BUF_B + soB;
        size_t gk = ((size_t)(kt64 * 64 + lrow)) * DK + lseg;
        size_t gb = (size_t)lrow * SEQ + kt64 * 64 + lseg;
        CPA16(b,                     pkhi + gk);
        CPA16(b + 16,                pkhi + gk + 8);
        CPA16(b + TILE_B,            pklo + gk);
        CPA16(b + TILE_B + 16,       pklo + gk + 8);
        CPA16(b + 2 * TILE_B,        pbhi + gb);
        CPA16(b + 2 * TILE_B + 16,   pbhi + gb + 8);
        CPA16(b + 3 * TILE_B,        pblo + gb);
        CPA16(b + 3 * TILE_B + 16,   pblo + gb + 8);
    };

    issue_tile(0, 0);
    CPA_COMMIT();

    for (int kt64 = 0; kt64 < SEQ / 64; kt64++) {
        const int curbuf = kt64 & 1;
        if (kt64 + 1 < SEQ / 64) {
            issue_tile(kt64 + 1, curbuf ^ 1);
            CPA_COMMIT();
            CPA_WAIT1();
        } else {
            CPA_WAIT0();
        }
        __syncthreads();

        const __nv_bfloat16* s_khi = (const __nv_bfloat16*)(smraw + curbuf * BUF_B);
        const __nv_bfloat16* s_klo = (const __nv_bfloat16*)(smraw + curbuf * BUF_B + TILE_B);
        const __nv_bfloat16* s_vhi = (const __nv_bfloat16*)(smraw + curbuf * BUF_B + 2 * TILE_B);
        const __nv_bfloat16* s_vlo = (const __nv_bfloat16*)(smraw + curbuf * BUF_B + 3 * TILE_B);

        // ---- S = Q K^T ----
        float sc[8][4];
        #pragma unroll
        for (int j = 0; j < 8; j++)
            #pragma unroll
            for (int i = 0; i < 4; i++) sc[j][i] = 0.f;

        #pragma unroll
        for (int j = 0; j < 8; j++) {
            int key = 8 * j + g;
            #pragma unroll
            for (int kk = 0; kk < 4; kk++) {
                int kc = 16 * kk + 2 * t;
                uint32_t bh0 = *(const uint32_t*)&s_khi[key * KSTR + kc];
                uint32_t bh1 = *(const uint32_t*)&s_khi[key * KSTR + kc + 8];
                uint32_t bl0 = *(const uint32_t*)&s_klo[key * KSTR + kc];
                uint32_t bl1 = *(const uint32_t*)&s_klo[key * KSTR + kc + 8];
                mma16816(sc[j], qh[kk], bh0, bh1);
                mma16816(sc[j], ql[kk], bh0, bh1);
                mma16816(sc[j], qh[kk], bl0, bl1);
            }
        }

        // ---- softmax (fixed max 8) + truncation split-pack into A-frags ----
        uint32_t pah[4][4], pal[4][4];
        #pragma unroll
        for (int kk = 0; kk < 4; kk++) {
            float e0a = __expf(fmaf(sc[2*kk][0],   0.125f, -8.f));
            float e0b = __expf(fmaf(sc[2*kk][1],   0.125f, -8.f));
            float e0c = __expf(fmaf(sc[2*kk][2],   0.125f, -8.f));
            float e0d = __expf(fmaf(sc[2*kk][3],   0.125f, -8.f));
            float e1a = __expf(fmaf(sc[2*kk+1][0], 0.125f, -8.f));
            float e1b = __expf(fmaf(sc[2*kk+1][1], 0.125f, -8.f));
            float e1c = __expf(fmaf(sc[2*kk+1][2], 0.125f, -8.f));
            float e1d = __expf(fmaf(sc[2*kk+1][3], 0.125f, -8.f));
            lac0 += e0a + e0b + e1a + e1b;
            lac1 += e0c + e0d + e1c + e1d;
            split2(e0a, e0b, pah[kk][0], pal[kk][0]);
            split2(e0c, e0d, pah[kk][1], pal[kk][1]);
            split2(e1a, e1b, pah[kk][2], pal[kk][2]);
            split2(e1c, e1d, pah[kk][3], pal[kk][3]);
        }

        // ---- O += P @ Vals ----
        #pragma unroll
        for (int j = 0; j < 8; j++) {
            int dd = 8 * j + g;
            #pragma unroll
            for (int kk = 0; kk < 4; kk++) {
                int kc = 16 * kk + 2 * t;
                uint32_t vh0 = *(const uint32_t*)&s_vhi[dd * KSTR + kc];
                uint32_t vh1 = *(const uint32_t*)&s_vhi[dd * KSTR + kc + 8];
                uint32_t vl0 = *(const uint32_t*)&s_vlo[dd * KSTR + kc];
                uint32_t vl1 = *(const uint32_t*)&s_vlo[dd * KSTR + kc + 8];
                mma16816(oc[j], pah[kk], vh0, vh1);
                mma16816(oc[j], pal[kk], vh0, vh1);
                mma16816(oc[j], pah[kk], vl0, vl1);
            }
        }
        __syncthreads();   // all reads done before this buffer is refilled
    }

    // ---- epilogue: normalize, store, ssq ----
    lac0 += __shfl_xor_sync(~0u, lac0, 1);
    lac0 += __shfl_xor_sync(~0u, lac0, 2);
    lac1 += __shfl_xor_sync(~0u, lac1, 1);
    lac1 += __shfl_xor_sync(~0u, lac1, 2);
    const float inv0 = 1.0f / lac0;
    const float inv1 = 1.0f / lac1;

    float* ob0 = qdst + ((size_t)bh * SEQ + q0 + m0 + g) * DK;
    float* ob1 = qdst + ((size_t)bh * SEQ + q0 + m0 + g + 8) * DK;
    const float* qr0 = qb + (size_t)(m0 + g) * DK;
    const float* qr1 = qb + (size_t)(m0 + g + 8) * DK;
    float local = 0.f;
    #pragma unroll
    for (int j = 0; j < 8; j++) {
        int c = 8 * j + 2 * t;
        float2 w0 = make_float2(oc[j][0] * inv0, oc[j][1] * inv0);
        float2 w1 = make_float2(oc[j][2] * inv1, oc[j][3] * inv1);
        *(float2*)(ob0 + c) = w0;
        *(float2*)(ob1 + c) = w1;
        if (!finalPass) {
            float2 a = *(const float2*)(qr0 + c);
            float2 b = *(const float2*)(qr1 + c);
            float d0 = w0.x - a.x, d1 = w0.y - a.y;
            float d2 = w1.x - b.x, d3 = w1.y - b.y;
            local += d0 * d0 + d1 * d1 + d2 * d2 + d3 * d3;
        }
    }
    if (!finalPass) {
        #pragma unroll
        for (int off = 16; off; off >>= 1)
            local += __shfl_xor_sync(~0u, local, off);
        if (lane == 0) atomicAdd(&g_ssq, local);
    }
}

// ---------------------------------------------------------------------------
__global__ void init_state_kernel() { g_cur = 0; g_ssq = 0.0f; }

// eps gate: flip current-q buffer iff ||new_q - q|| > 1e-4; reset ssq.
__global__ void gate_flip_kernel()
{
    if (g_ssq > 1e-8f) g_cur ^= 1;
    g_ssq = 0.0f;
}

// ---------------------------------------------------------------------------
// prep_o: gather final attn output -> go hi/lo [token][512] row-major.
// Final O lives in the buffer OPPOSITE to g_cur (attn always writes !g_cur).
// ---------------------------------------------------------------------------
__global__ __launch_bounds__(256)
void prep_o()
{
    const float* src = g_cur ? g_q : g_nq;
    int i4 = blockIdx.x * 256 + threadIdx.x;
    int dq = (i4 & 15) * 4;
    int tk = i4 >> 4;
    float4 v = *(const float4*)(src + (size_t)tk * DK + dq);
    int bh = tk >> 10, s = tk & 1023;
    int b = bh >> 3, h = bh & 7;
    size_t o = ((size_t)(b * SEQ + s)) * DMODEL + h * 64 + dq;
    uint32_t h01, l01, h23, l23;
    split2(v.x, v.y, h01, l01);
    split2(v.z, v.w, h23, l23);
    *(uint32_t*)&go_hi[o]     = h01;
    *(uint32_t*)&go_hi[o + 2] = h23;
    *(uint32_t*)&go_lo[o]     = l01;
    *(uint32_t*)&go_lo[o + 2] = l23;
}

// ---------------------------------------------------------------------------
extern "C" void kernel_launch(void* const* d_in, const int* in_sizes, int n_in,
                              void* d_out, int out_size)
{
    const float* x     = (const float*)d_in[0];
    const float* Wq    = (const float*)d_in[1];
    const float* bq    = (const float*)d_in[2];
    const float* Wk    = (const float*)d_in[3];
    const float* bk    = (const float*)d_in[4];
    const float* Wv    = (const float*)d_in[5];
    const float* bv    = (const float*)d_in[6];
    const float* Wo    = (const float*)d_in[7];
    const float* bo    = (const float*)d_in[8];
    const float* gamma = (const float*)d_in[9];
    const float* beta  = (const float*)d_in[10];
    float* out = (float*)d_out;

    const int projSmem = (int)sizeof(Proj2Smem);   // 73728 B
    cudaFuncSetAttribute(qkv_mma,
                         cudaFuncAttributeMaxDynamicSharedMemorySize, projSmem);
    cudaFuncSetAttribute(out_mma,
                         cudaFuncAttributeMaxDynamicSharedMemorySize, projSmem);
    cudaFuncSetAttribute(attn_mma,
                         cudaFuncAttributeMaxDynamicSharedMemorySize, ATTN_SMEM);

    // 0. state init + hi/lo splits of x and W^T
    init_state_kernel<<<1, 1>>>();
    prep_x<<<XW_ELEMS / 4 / 256, 256>>>(x);
    prep_w<<<dim3(8, 8, 4), 256>>>(Wq, Wk, Wv, Wo);
    // 1. QKV projections, N=128 (2 heads/block) + fused LayerNorm
    qkv_mma<<<dim3(TOKENS / 128, 12), 256, projSmem>>>(bq, bk, bv, gamma, beta);
    // 2. bf16 hi/lo splits of K, K^T, V^T
    prep_kernel<<<dim3(SEQ / 64, BHD), 256>>>();
    // 3. Hopfield update iterations (values = K), buffer ping-pong eps gate
    for (int it = 0; it < 3; it++) {
        attn_mma<<<dim3(SEQ / 128, BHD), 256, ATTN_SMEM>>>(0);
        gate_flip_kernel<<<1, 1>>>();
    }
    // 4. Final retrieval (values = V)
    attn_mma<<<dim3(SEQ / 128, BHD), 256, ATTN_SMEM>>>(1);
    // 5. Output projection, N=128
    prep_o<<<XW_ELEMS / 4 / 256, 256>>>();
    out_mma<<<dim3(TOKENS / 128, DMODEL / 128), 256, projSmem>>>(bo, out);
}

// round 16
// speedup vs baseline: 1.2378x; 1.0237x over previous
#include <cuda_runtime.h>
#include <cuda_bf16.h>
#include <cstdint>

#define NHEADS   8
#define DK       64
#define SEQ      1024
#define BATCH    8
#define DMODEL   512
#define BHD      (BATCH*NHEADS)          // 64
#define TOKENS   (BATCH*SEQ)             // 8192
#define QKV_ELEMS (BHD*SEQ*DK)           // 4194304
#define XW_ELEMS (TOKENS*DMODEL)         // 4194304

// ---------------- scratch (device globals; no allocation allowed) ----------
__device__ float g_q[QKV_ELEMS];
__device__ float g_k[QKV_ELEMS];
__device__ float g_v[QKV_ELEMS];
__device__ float g_nq[QKV_ELEMS];
__device__ float g_ssq;
__device__ int   g_cur;                  // 0: current q in g_q, 1: in g_nq

// bf16 hi/lo splits (built per launch)
__device__ __align__(256) __nv_bfloat16 gk_hi[QKV_ELEMS];   // K, K-major
__device__ __align__(256) __nv_bfloat16 gk_lo[QKV_ELEMS];
__device__ __align__(256) __nv_bfloat16 gkt_hi[QKV_ELEMS];  // K^T, d-major
__device__ __align__(256) __nv_bfloat16 gkt_lo[QKV_ELEMS];
__device__ __align__(256) __nv_bfloat16 gvt_hi[QKV_ELEMS];  // V^T, d-major
__device__ __align__(256) __nv_bfloat16 gvt_lo[QKV_ELEMS];
__device__ __align__(256) __nv_bfloat16 gx_hi[XW_ELEMS];    // x, row-major
__device__ __align__(256) __nv_bfloat16 gx_lo[XW_ELEMS];
__device__ __align__(256) __nv_bfloat16 gw_hi[4*DMODEL*DMODEL]; // W^T [n][k]
__device__ __align__(256) __nv_bfloat16 gw_lo[4*DMODEL*DMODEL];
__device__ __align__(256) __nv_bfloat16 go_hi[XW_ELEMS];    // attn out gathered
__device__ __align__(256) __nv_bfloat16 go_lo[XW_ELEMS];

// ---------------- helpers ----------------------------------------------------
// Truncation split of a pair: hp = {bf16_trunc(a), bf16_trunc(b)} via PRMT,
// lp = {bf16_rn(a-hi_a), bf16_rn(b-hi_b)} via one cvt.rn.bf16x2.
__device__ __forceinline__ void split2(float a, float b,
                                       uint32_t& hp, uint32_t& lp) {
    uint32_t ua = __float_as_uint(a), ub = __float_as_uint(b);
    float ha = __uint_as_float(ua & 0xFFFF0000u);
    float hb = __uint_as_float(ub & 0xFFFF0000u);
    asm("prmt.b32 %0, %1, %2, 0x7632;" : "=r"(hp) : "r"(ua), "r"(ub));
    float la = a - ha, lb = b - hb;
    asm("cvt.rn.bf16x2.f32 %0, %1, %2;" : "=r"(lp) : "f"(lb), "f"(la));
}
// m16n8k16 bf16 MMA, f32 accumulate (sm_80 baseline PTX -> HMMA on sm_103a)
__device__ __forceinline__ void mma16816(float c[4], const uint32_t a[4],
                                         uint32_t b0, uint32_t b1) {
    asm volatile(
        "mma.sync.aligned.m16n8k16.row.col.f32.bf16.bf16.f32 "
        "{%0,%1,%2,%3}, {%4,%5,%6,%7}, {%8,%9}, {%0,%1,%2,%3};"
        : "+f"(c[0]), "+f"(c[1]), "+f"(c[2]), "+f"(c[3])
        : "r"(a[0]), "r"(a[1]), "r"(a[2]), "r"(a[3]), "r"(b0), "r"(b1));
}
// cp.async 16B (sm_80 baseline)
#define CPA16(dst_u32, src_ptr) \
    asm volatile("cp.async.cg.shared.global [%0], [%1], 16;" \
                 :: "r"(dst_u32), "l"(src_ptr))
#define CPA_COMMIT() asm volatile("cp.async.commit_group;" ::: "memory")
#define CPA_WAIT1()  asm volatile("cp.async.wait_group 1;" ::: "memory")
#define CPA_WAIT0()  asm volatile("cp.async.wait_group 0;" ::: "memory")

__device__ __forceinline__ uint32_t smem_addr_u32(const void* p) {
    uint32_t a;
    asm("{ .reg .u64 t; cvta.to.shared.u64 t, %1; cvt.u32.u64 %0, t; }"
        : "=r"(a) : "l"(p));
    return a;
}

#define KSTR 72   // smem row stride in bf16 (144 B) -> conflict-free fragments

// ---------------------------------------------------------------------------
// prep_x: split x into bf16 hi/lo (row-major). Also initializes gate state.
// ---------------------------------------------------------------------------
__global__ __launch_bounds__(256)
void prep_x(const float* __restrict__ x)
{
    if (blockIdx.x == 0 && threadIdx.x == 0) { g_cur = 0; g_ssq = 0.0f; }
    int i = (blockIdx.x * 256 + threadIdx.x) * 4;
    float4 v = *(const float4*)(x + i);
    uint32_t h01, l01, h23, l23;
    split2(v.x, v.y, h01, l01);
    split2(v.z, v.w, h23, l23);
    *(uint32_t*)&gx_hi[i]     = h01;
    *(uint32_t*)&gx_hi[i + 2] = h23;
    *(uint32_t*)&gx_lo[i]     = l01;
    *(uint32_t*)&gx_lo[i + 2] = l23;
}

// ---------------------------------------------------------------------------
// prep_w: transpose each W (k-major 512x512) into [n][k] and split hi/lo.
// ---------------------------------------------------------------------------
__global__ __launch_bounds__(256)
void prep_w(const float* __restrict__ Wq, const float* __restrict__ Wk,
            const float* __restrict__ Wv, const float* __restrict__ Wo)
{
    __shared__ float tile[64][65];
    const int z = blockIdx.z;
    const float* W = (z == 0) ? Wq : (z == 1) ? Wk : (z == 2) ? Wv : Wo;
    const int k0 = blockIdx.x * 64, n0 = blockIdx.y * 64;
    const int tid = threadIdx.x;

    for (int idx = tid; idx < 4096; idx += 256) {
        int r = idx >> 6, c = idx & 63;
        tile[r][c] = W[(size_t)(k0 + r) * DMODEL + n0 + c];
    }
    __syncthreads();
    for (int idx = tid * 2; idx < 4096; idx += 512) {
        int r = idx >> 6, c = idx & 63;           // r: n-local, c: k-local
        uint32_t hp, lp;
        split2(tile[c][r], tile[c + 1][r], hp, lp);
        size_t o = (size_t)z * DMODEL * DMODEL + (size_t)(n0 + r) * DMODEL + k0 + c;
        *(uint32_t*)&gw_hi[o] = hp;
        *(uint32_t*)&gw_lo[o] = lp;
    }
}

// ---------------------------------------------------------------------------
// Wide (N=128) SMEM-staged HMMA projection body (R15, passing — unchanged).
// ---------------------------------------------------------------------------
struct Proj2Smem {
    __nv_bfloat16 xhi[128 * KSTR];
    __nv_bfloat16 xlo[128 * KSTR];
    __nv_bfloat16 whi[128 * KSTR];
    __nv_bfloat16 wlo[128 * KSTR];
};

__device__ __forceinline__ void proj2_tiles_mma(
    Proj2Smem* s,
    const __nv_bfloat16* __restrict__ ahi, const __nv_bfloat16* __restrict__ alo,
    const __nv_bfloat16* __restrict__ bhi, const __nv_bfloat16* __restrict__ blo,
    int row0, float acc[16][4])
{
    const int tid = threadIdx.x;
    const int warp = tid >> 5, lane = tid & 31;
    const int g = lane >> 2, t = lane & 3;
    const int m0 = warp * 16;
    const int lrow = tid >> 2, lseg = (tid & 3) * 16;

    for (int kt = 0; kt < DMODEL / 64; kt++) {
        const int k0 = kt * 64;
        __syncthreads();
        #pragma unroll
        for (int half = 0; half < 2; half++) {
            int xr = half * 64 + lrow;
            size_t gx = (size_t)(row0 + xr) * DMODEL + k0 + lseg;
            uint32_t so = xr * KSTR + lseg;
            *(uint4*)&s->xhi[so]     = *(const uint4*)(ahi + gx);
            *(uint4*)&s->xhi[so + 8] = *(const uint4*)(ahi + gx + 8);
            *(uint4*)&s->xlo[so]     = *(const uint4*)(alo + gx);
            *(uint4*)&s->xlo[so + 8] = *(const uint4*)(alo + gx + 8);
            size_t gw = (size_t)xr * DMODEL + k0 + lseg;   // n-row xr of B
            *(uint4*)&s->whi[so]     = *(const uint4*)(bhi + gw);
            *(uint4*)&s->whi[so + 8] = *(const uint4*)(bhi + gw + 8);
            *(uint4*)&s->wlo[so]     = *(const uint4*)(blo + gw);
            *(uint4*)&s->wlo[so + 8] = *(const uint4*)(blo + gw + 8);
        }
        __syncthreads();

        #pragma unroll
        for (int kk = 0; kk < 4; kk++) {
            const int kc = 16 * kk + 2 * t;
            uint32_t ah[4], al[4];
            ah[0] = *(const uint32_t*)&s->xhi[(m0 + g) * KSTR + kc];
            ah[1] = *(const uint32_t*)&s->xhi[(m0 + g + 8) * KSTR + kc];
            ah[2] = *(const uint32_t*)&s->xhi[(m0 + g) * KSTR + kc + 8];
            ah[3] = *(const uint32_t*)&s->xhi[(m0 + g + 8) * KSTR + kc + 8];
            al[0] = *(const uint32_t*)&s->xlo[(m0 + g) * KSTR + kc];
            al[1] = *(const uint32_t*)&s->xlo[(m0 + g + 8) * KSTR + kc];
            al[2] = *(const uint32_t*)&s->xlo[(m0 + g) * KSTR + kc + 8];
            al[3] = *(const uint32_t*)&s->xlo[(m0 + g + 8) * KSTR + kc + 8];
            #pragma unroll
            for (int j = 0; j < 16; j++) {
                const int n = 8 * j + g;
                uint32_t bh0 = *(const uint32_t*)&s->whi[n * KSTR + kc];
                uint32_t bh1 = *(const uint32_t*)&s->whi[n * KSTR + kc + 8];
                uint32_t bl0 = *(const uint32_t*)&s->wlo[n * KSTR + kc];
                uint32_t bl1 = *(const uint32_t*)&s->wlo[n * KSTR + kc + 8];
                mma16816(acc[j], ah, bh0, bh1);
                mma16816(acc[j], al, bh0, bh1);
                mma16816(acc[j], ah, bl0, bl1);
            }
        }
    }
}

// ---------------------------------------------------------------------------
// QKV projection, N=128 (two heads per block) + fused per-head LayerNorm.
// grid = (TOKENS/128, 12): blockIdx.y = mat*4 + headpair. (R15.)
// ---------------------------------------------------------------------------
__global__ __launch_bounds__(256)
void qkv_mma(const float* __restrict__ bq, const float* __restrict__ bk,
             const float* __restrict__ bv,
             const float* __restrict__ gamma, const float* __restrict__ beta)
{
    extern __shared__ char smraw[];
    Proj2Smem* s = (Proj2Smem*)smraw;

    const int mat   = blockIdx.y >> 2;
    const int head0 = (blockIdx.y & 3) * 2;
    const int row0  = blockIdx.x * 128;
    const int tid = threadIdx.x;
    const int warp = tid >> 5, lane = tid & 31;
    const int g = lane >> 2, t = lane & 3;
    const int m0 = warp * 16;

    const float* bias = (mat == 0) ? bq : (mat == 1) ? bk : bv;
    float*       out  = (mat == 0) ? g_q : (mat == 1) ? g_k : g_v;
    const __nv_bfloat16* wh = gw_hi + (size_t)mat * DMODEL * DMODEL
                            + (size_t)head0 * 64 * DMODEL;
    const __nv_bfloat16* wl = gw_lo + (size_t)mat * DMODEL * DMODEL
                            + (size_t)head0 * 64 * DMODEL;

    float acc[16][4];
    #pragma unroll
    for (int j = 0; j < 16; j++)
        #pragma unroll
        for (int i = 0; i < 4; i++) acc[j][i] = 0.f;

    proj2_tiles_mma(s, gx_hi, gx_lo, wh, wl, row0, acc);

    #pragma unroll
    for (int j = 0; j < 16; j++) {
        int head = head0 + (j >> 3);
        int col = (j & 7) * 8 + 2 * t;
        float b0v = bias[head * 64 + col];
        float b1v = bias[head * 64 + col + 1];
        acc[j][0] += b0v; acc[j][1] += b1v;
        acc[j][2] += b0v; acc[j][3] += b1v;
    }

    if (mat < 2) {
        #pragma unroll
        for (int h = 0; h < 2; h++) {
            const int jb = h * 8;
            float s0 = 0.f, s1 = 0.f;
            #pragma unroll
            for (int jj = 0; jj < 8; jj++) {
                s0 += acc[jb + jj][0] + acc[jb + jj][1];
                s1 += acc[jb + jj][2] + acc[jb + jj][3];
            }
            s0 += __shfl_xor_sync(~0u, s0, 1); s0 += __shfl_xor_sync(~0u, s0, 2);
            s1 += __shfl_xor_sync(~0u, s1, 1); s1 += __shfl_xor_sync(~0u, s1, 2);
            float mu0 = s0 * (1.f / 64.f), mu1 = s1 * (1.f / 64.f);
            float v0 = 0.f, v1 = 0.f;
            #pragma unroll
            for (int jj = 0; jj < 8; jj++) {
                acc[jb + jj][0] -= mu0; acc[jb + jj][1] -= mu0;
                acc[jb + jj][2] -= mu1; acc[jb + jj][3] -= mu1;
                v0 += acc[jb + jj][0] * acc[jb + jj][0]
                    + acc[jb + jj][1] * acc[jb + jj][1];
                v1 += acc[jb + jj][2] * acc[jb + jj][2]
                    + acc[jb + jj][3] * acc[jb + jj][3];
            }
            v0 += __shfl_xor_sync(~0u, v0, 1); v0 += __shfl_xor_sync(~0u, v0, 2);
            v1 += __shfl_xor_sync(~0u, v1, 1); v1 += __shfl_xor_sync(~0u, v1, 2);
            float inv0 = rsqrtf(v0 * (1.f / 64.f) + 1e-5f);
            float inv1 = rsqrtf(v1 * (1.f / 64.f) + 1e-5f);
            #pragma unroll
            for (int jj = 0; jj < 8; jj++) {
                int col = jj * 8 + 2 * t;
                float ga0 = gamma[col], ga1 = gamma[col + 1];
                float be0 = beta[col],  be1 = beta[col + 1];
                acc[jb + jj][0] = acc[jb + jj][0] * inv0 * ga0 + be0;
                acc[jb + jj][1] = acc[jb + jj][1] * inv0 * ga1 + be1;
                acc[jb + jj][2] = acc[jb + jj][2] * inv1 * ga0 + be0;
                acc[jb + jj][3] = acc[jb + jj][3] * inv1 * ga1 + be1;
            }
        }
    }

    const int r0 = row0 + m0 + g, r1 = r0 + 8;
    const int b0i = r0 >> 10, ss0 = r0 & 1023;
    const int b1i = r1 >> 10, ss1 = r1 & 1023;
    #pragma unroll
    for (int h = 0; h < 2; h++) {
        int head = head0 + h;
        float* o0 = out + (((size_t)b0i * NHEADS + head) * SEQ + ss0) * DK;
        float* o1 = out + (((size_t)b1i * NHEADS + head) * SEQ + ss1) * DK;
        #pragma unroll
        for (int jj = 0; jj < 8; jj++) {
            int j = h * 8 + jj;
            *(float2*)(o0 + jj * 8 + 2 * t) = make_float2(acc[j][0], acc[j][1]);
            *(float2*)(o1 + jj * 8 + 2 * t) = make_float2(acc[j][2], acc[j][3]);
        }
    }
}

// ---------------------------------------------------------------------------
// Output projection, N=128. grid = (TOKENS/128, DMODEL/128). (R15.)
// ---------------------------------------------------------------------------
__global__ __launch_bounds__(256)
void out_mma(const float* __restrict__ bo, float* __restrict__ C)
{
    extern __shared__ char smraw[];
    Proj2Smem* s = (Proj2Smem*)smraw;

    const int n0   = blockIdx.y * 128;
    const int row0 = blockIdx.x * 128;
    const int tid = threadIdx.x;
    const int warp = tid >> 5, lane = tid & 31;
    const int g = lane >> 2, t = lane & 3;
    const int m0 = warp * 16;

    const __nv_bfloat16* wh = gw_hi + (size_t)3 * DMODEL * DMODEL
                            + (size_t)n0 * DMODEL;
    const __nv_bfloat16* wl = gw_lo + (size_t)3 * DMODEL * DMODEL
                            + (size_t)n0 * DMODEL;

    float acc[16][4];
    #pragma unroll
    for (int j = 0; j < 16; j++)
        #pragma unroll
        for (int i = 0; i < 4; i++) acc[j][i] = 0.f;

    proj2_tiles_mma(s, go_hi, go_lo, wh, wl, row0, acc);

    const int r0 = row0 + m0 + g, r1 = r0 + 8;
    #pragma unroll
    for (int j = 0; j < 16; j++) {
        int c = n0 + 8 * j + 2 * t;
        float b0v = bo[c], b1v = bo[c + 1];
        *(float2*)(C + (size_t)r0 * DMODEL + c) =
            make_float2(acc[j][0] + b0v, acc[j][1] + b1v);
        *(float2*)(C + (size_t)r1 * DMODEL + c) =
            make_float2(acc[j][2] + b0v, acc[j][3] + b1v);
    }
}

// ---------------------------------------------------------------------------
// Prep (vectorized): split K -> bf16 hi/lo (K-major), K^T, V^T -> hi/lo
// (d-major). 2 elements/thread, split2, 4B stores throughout.
// ---------------------------------------------------------------------------
__global__ __launch_bounds__(256)
void prep_kernel()
{
    __shared__ float ts[64][65];
    const int bh = blockIdx.y;
    const int s0 = blockIdx.x * 64;
    const int tid = threadIdx.x;

    // K: hi/lo split (K-major) + stage for transpose
    #pragma unroll
    for (int p = tid; p < 2048; p += 256) {
        int r = p >> 5, d = (p & 31) * 2;
        float2 v = *(const float2*)(g_k + ((size_t)bh * SEQ + s0 + r) * DK + d);
        uint32_t hp, lp;
        split2(v.x, v.y, hp, lp);
        size_t o = ((size_t)bh * SEQ + s0 + r) * DK + d;
        *(uint32_t*)&gk_hi[o] = hp;
        *(uint32_t*)&gk_lo[o] = lp;
        ts[r][d] = v.x; ts[r][d + 1] = v.y;
    }
    __syncthreads();
    // K^T (d-major)
    #pragma unroll
    for (int p = tid; p < 2048; p += 256) {
        int d = p >> 5, ss = (p & 31) * 2;
        uint32_t hp, lp;
        split2(ts[ss][d], ts[ss + 1][d], hp, lp);
        size_t o = ((size_t)bh * DK + d) * SEQ + s0 + ss;
        *(uint32_t*)&gkt_hi[o] = hp;
        *(uint32_t*)&gkt_lo[o] = lp;
    }
    __syncthreads();
    // V staged
    #pragma unroll
    for (int p = tid; p < 2048; p += 256) {
        int r = p >> 5, d = (p & 31) * 2;
        float2 v = *(const float2*)(g_v + ((size_t)bh * SEQ + s0 + r) * DK + d);
        ts[r][d] = v.x; ts[r][d + 1] = v.y;
    }
    __syncthreads();
    // V^T (d-major)
    #pragma unroll
    for (int p = tid; p < 2048; p += 256) {
        int d = p >> 5, ss = (p & 31) * 2;
        uint32_t hp, lp;
        split2(ts[ss][d], ts[ss + 1][d], hp, lp);
        size_t o = ((size_t)bh * DK + d) * SEQ + s0 + ss;
        *(uint32_t*)&gvt_hi[o] = hp;
        *(uint32_t*)&gvt_lo[o] = lp;
    }
}

// ---------------------------------------------------------------------------
// Attention (R11/R15 design): mma.sync + cp.async double-buffered tiles +
// truncation split-pack. Buffer ping-pong eps gate via g_cur.
// finalPass==1: epilogue writes gathered go_hi/go_lo directly (prep_o fused).
// grid = (SEQ/128, BHD), 256 threads, dyn smem 73728 B.
// ---------------------------------------------------------------------------
#define TILE_B   9216          // one region: 64*KSTR*2 bytes
#define BUF_B    (4*TILE_B)    // khi,klo,vhi,vlo
#define ATTN_SMEM (2*BUF_B)    // 73728

__global__ __launch_bounds__(256)
void attn_mma(int finalPass)
{
    extern __shared__ char smraw[];
    const uint32_t sbase = smem_addr_u32(smraw);

    const int tid  = threadIdx.x;
    const int warp = tid >> 5;
    const int lane = tid & 31;
    const int g = lane >> 2;
    const int t = lane & 3;
    const int bh = blockIdx.y;
    const int q0 = blockIdx.x * 128;
    const int m0 = warp * 16;

    const int cur = g_cur;
    const float* qsrc = cur ? g_nq : g_q;
    float*       qdst = cur ? g_q : g_nq;
    const float* qb = qsrc + ((size_t)bh * SEQ + q0) * DK;

    // ---- Q fragments (hi/lo) via truncation split ----
    uint32_t qh[4][4], ql[4][4];
    {
        const float* r0p = qb + (size_t)(m0 + g) * DK;
        const float* r1p = qb + (size_t)(m0 + g + 8) * DK;
        #pragma unroll
        for (int kt = 0; kt < 4; kt++) {
            float2 v00 = *(const float2*)(r0p + 16 * kt + 2 * t);
            float2 v10 = *(const float2*)(r1p + 16 * kt + 2 * t);
            float2 v01 = *(const float2*)(r0p + 16 * kt + 2 * t + 8);
            float2 v11 = *(const float2*)(r1p + 16 * kt + 2 * t + 8);
            split2(v00.x, v00.y, qh[kt][0], ql[kt][0]);
            split2(v10.x, v10.y, qh[kt][1], ql[kt][1]);
            split2(v01.x, v01.y, qh[kt][2], ql[kt][2]);
            split2(v11.x, v11.y, qh[kt][3], ql[kt][3]);
        }
    }

    float oc[8][4];
    #pragma unroll
    for (int j = 0; j < 8; j++)
        #pragma unroll
        for (int i = 0; i < 4; i++) oc[j][i] = 0.f;
    float lac0 = 0.f, lac1 = 0.f;

    const __nv_bfloat16* pkhi = gk_hi + (size_t)bh * SEQ * DK;
    const __nv_bfloat16* pklo = gk_lo + (size_t)bh * SEQ * DK;
    const __nv_bfloat16* pbhi = (finalPass ? gvt_hi : gkt_hi) + (size_t)bh * DK * SEQ;
    const __nv_bfloat16* pblo = (finalPass ? gvt_lo : gkt_lo) + (size_t)bh * DK * SEQ;

    const int lrow = tid >> 2;             // 0..63
    const int lseg = (tid & 3) * 16;       // bf16 col offset (0,16,32,48)
    const uint32_t soB = (uint32_t)(lrow * KSTR + lseg) * 2;   // byte offset

    auto issue_tile = [&](int kt64, int buf) {
        uint32_t b = sbase + buf * BUF_B + soB;
        size_t gk = ((size_t)(kt64 * 64 + lrow)) * DK + lseg;
        size_t gb = (size_t)lrow * SEQ + kt64 * 64 + lseg;
        CPA16(b,                     pkhi + gk);
        CPA16(b + 16,                pkhi + gk + 8);
        CPA16(b + TILE_B,            pklo + gk);
        CPA16(b + TILE_B + 16,       pklo + gk + 8);
        CPA16(b + 2 * TILE_B,        pbhi + gb);
        CPA16(b + 2 * TILE_B + 16,   pbhi + gb + 8);
        CPA16(b + 3 * TILE_B,        pblo + gb);
        CPA16(b + 3 * TILE_B + 16,   pblo + gb + 8);
    };

    issue_tile(0, 0);
    CPA_COMMIT();

    for (int kt64 = 0; kt64 < SEQ / 64; kt64++) {
        const int curbuf = kt64 & 1;
        if (kt64 + 1 < SEQ / 64) {
            issue_tile(kt64 + 1, curbuf ^ 1);
            CPA_COMMIT();
            CPA_WAIT1();
        } else {
            CPA_WAIT0();
        }
        __syncthreads();

        const __nv_bfloat16* s_khi = (const __nv_bfloat16*)(smraw + curbuf * BUF_B);
        const __nv_bfloat16* s_klo = (const __nv_bfloat16*)(smraw + curbuf * BUF_B + TILE_B);
        const __nv_bfloat16* s_vhi = (const __nv_bfloat16*)(smraw + curbuf * BUF_B + 2 * TILE_B);
        const __nv_bfloat16* s_vlo = (const __nv_bfloat16*)(smraw + curbuf * BUF_B + 3 * TILE_B);

        // ---- S = Q K^T ----
        float sc[8][4];
        #pragma unroll
        for (int j = 0; j < 8; j++)
            #pragma unroll
            for (int i = 0; i < 4; i++) sc[j][i] = 0.f;

        #pragma unroll
        for (int j = 0; j < 8; j++) {
            int key = 8 * j + g;
            #pragma unroll
            for (int kk = 0; kk < 4; kk++) {
                int kc = 16 * kk + 2 * t;
                uint32_t bh0 = *(const uint32_t*)&s_khi[key * KSTR + kc];
                uint32_t bh1 = *(const uint32_t*)&s_khi[key * KSTR + kc + 8];
                uint32_t bl0 = *(const uint32_t*)&s_klo[key * KSTR + kc];
                uint32_t bl1 = *(const uint32_t*)&s_klo[key * KSTR + kc + 8];
                mma16816(sc[j], qh[kk], bh0, bh1);
                mma16816(sc[j], ql[kk], bh0, bh1);
                mma16816(sc[j], qh[kk], bl0, bl1);
            }
        }

        // ---- softmax (fixed max 8) + truncation split-pack into A-frags ----
        uint32_t pah[4][4], pal[4][4];
        #pragma unroll
        for (int kk = 0; kk < 4; kk++) {
            float e0a = __expf(fmaf(sc[2*kk][0],   0.125f, -8.f));
            float e0b = __expf(fmaf(sc[2*kk][1],   0.125f, -8.f));
            float e0c = __expf(fmaf(sc[2*kk][2],   0.125f, -8.f));
            float e0d = __expf(fmaf(sc[2*kk][3],   0.125f, -8.f));
            float e1a = __expf(fmaf(sc[2*kk+1][0], 0.125f, -8.f));
            float e1b = __expf(fmaf(sc[2*kk+1][1], 0.125f, -8.f));
            float e1c = __expf(fmaf(sc[2*kk+1][2], 0.125f, -8.f));
            float e1d = __expf(fmaf(sc[2*kk+1][3], 0.125f, -8.f));
            lac0 += e0a + e0b + e1a + e1b;
            lac1 += e0c + e0d + e1c + e1d;
            split2(e0a, e0b, pah[kk][0], pal[kk][0]);
            split2(e0c, e0d, pah[kk][1], pal[kk][1]);
            split2(e1a, e1b, pah[kk][2], pal[kk][2]);
            split2(e1c, e1d, pah[kk][3], pal[kk][3]);
        }

        // ---- O += P @ Vals ----
        #pragma unroll
        for (int j = 0; j < 8; j++) {
            int dd = 8 * j + g;
            #pragma unroll
            for (int kk = 0; kk < 4; kk++) {
                int kc = 16 * kk + 2 * t;
                uint32_t vh0 = *(const uint32_t*)&s_vhi[dd * KSTR + kc];
                uint32_t vh1 = *(const uint32_t*)&s_vhi[dd * KSTR + kc + 8];
                uint32_t vl0 = *(const uint32_t*)&s_vlo[dd * KSTR + kc];
                uint32_t vl1 = *(const uint32_t*)&s_vlo[dd * KSTR + kc + 8];
                mma16816(oc[j], pah[kk], vh0, vh1);
                mma16816(oc[j], pal[kk], vh0, vh1);
                mma16816(oc[j], pah[kk], vl0, vl1);
            }
        }
        __syncthreads();   // all reads done before this buffer is refilled
    }

    // ---- epilogue: normalize; store O (+ ssq) or gathered go hi/lo ----
    lac0 += __shfl_xor_sync(~0u, lac0, 1);
    lac0 += __shfl_xor_sync(~0u, lac0, 2);
    lac1 += __shfl_xor_sync(~0u, lac1, 1);
    lac1 += __shfl_xor_sync(~0u, lac1, 2);
    const float inv0 = 1.0f / lac0;
    const float inv1 = 1.0f / lac1;

    if (!finalPass) {
        float* ob0 = qdst + ((size_t)bh * SEQ + q0 + m0 + g) * DK;
        float* ob1 = qdst + ((size_t)bh * SEQ + q0 + m0 + g + 8) * DK;
        const float* qr0 = qb + (size_t)(m0 + g) * DK;
        const float* qr1 = qb + (size_t)(m0 + g + 8) * DK;
        float local = 0.f;
        #pragma unroll
        for (int j = 0; j < 8; j++) {
            int c = 8 * j + 2 * t;
            float2 w0 = make_float2(oc[j][0] * inv0, oc[j][1] * inv0);
            float2 w1 = make_float2(oc[j][2] * inv1, oc[j][3] * inv1);
            *(float2*)(ob0 + c) = w0;
            *(float2*)(ob1 + c) = w1;
            float2 a = *(const float2*)(qr0 + c);
            float2 b = *(const float2*)(qr1 + c);
            float d0 = w0.x - a.x, d1 = w0.y - a.y;
            float d2 = w1.x - b.x, d3 = w1.y - b.y;
            local += d0 * d0 + d1 * d1 + d2 * d2 + d3 * d3;
        }
        #pragma unroll
        for (int off = 16; off; off >>= 1)
            local += __shfl_xor_sync(~0u, local, off);
        if (lane == 0) atomicAdd(&g_ssq, local);
    } else {
        // gathered bf16 hi/lo write (prep_o fused): token = b*SEQ + s,
        // column = h*64 + c within DMODEL.
        const int b = bh >> 3, h = bh & 7;
        const int s0r = q0 + m0 + g, s1r = s0r + 8;
        size_t o0 = ((size_t)(b * SEQ + s0r)) * DMODEL + h * 64;
        size_t o1 = ((size_t)(b * SEQ + s1r)) * DMODEL + h * 64;
        #pragma unroll
        for (int j = 0; j < 8; j++) {
            int c = 8 * j + 2 * t;
            uint32_t hp0, lp0, hp1, lp1;
            split2(oc[j][0] * inv0, oc[j][1] * inv0, hp0, lp0);
            split2(oc[j][2] * inv1, oc[j][3] * inv1, hp1, lp1);
            *(uint32_t*)&go_hi[o0 + c] = hp0;
            *(uint32_t*)&go_lo[o0 + c] = lp0;
            *(uint32_t*)&go_hi[o1 + c] = hp1;
            *(uint32_t*)&go_lo[o1 + c] = lp1;
        }
    }
}

// ---------------------------------------------------------------------------
// eps gate: flip current-q buffer iff ||new_q - q|| > 1e-4; reset ssq.
__global__ void gate_flip_kernel()
{
    if (g_ssq > 1e-8f) g_cur ^= 1;
    g_ssq = 0.0f;
}

// ---------------------------------------------------------------------------
extern "C" void kernel_launch(void* const* d_in, const int* in_sizes, int n_in,
                              void* d_out, int out_size)
{
    const float* x     = (const float*)d_in[0];
    const float* Wq    = (const float*)d_in[1];
    const float* bq    = (const float*)d_in[2];
    const float* Wk    = (const float*)d_in[3];
    const float* bk    = (const float*)d_in[4];
    const float* Wv    = (const float*)d_in[5];
    const float* bv    = (const float*)d_in[6];
    const float* Wo    = (const float*)d_in[7];
    const float* bo    = (const float*)d_in[8];
    const float* gamma = (const float*)d_in[9];
    const float* beta  = (const float*)d_in[10];
    float* out = (float*)d_out;

    const int projSmem = (int)sizeof(Proj2Smem);   // 73728 B
    cudaFuncSetAttribute(qkv_mma,
                         cudaFuncAttributeMaxDynamicSharedMemorySize, projSmem);
    cudaFuncSetAttribute(out_mma,
                         cudaFuncAttributeMaxDynamicSharedMemorySize, projSmem);
    cudaFuncSetAttribute(attn_mma,
                         cudaFuncAttributeMaxDynamicSharedMemorySize, ATTN_SMEM);

    // 0. hi/lo splits of x (incl. gate-state init) and W^T
    prep_x<<<XW_ELEMS / 4 / 256, 256>>>(x);
    prep_w<<<dim3(8, 8, 4), 256>>>(Wq, Wk, Wv, Wo);
    // 1. QKV projections, N=128 (2 heads/block) + fused LayerNorm
    qkv_mma<<<dim3(TOKENS / 128, 12), 256, projSmem>>>(bq, bk, bv, gamma, beta);
    // 2. bf16 hi/lo splits of K, K^T, V^T (vectorized)
    prep_kernel<<<dim3(SEQ / 64, BHD), 256>>>();
    // 3. Hopfield update iterations (values = K), buffer ping-pong eps gate
    for (int it = 0; it < 3; it++) {
        attn_mma<<<dim3(SEQ / 128, BHD), 256, ATTN_SMEM>>>(0);
        gate_flip_kernel<<<1, 1>>>();
    }
    // 4. Final retrieval (values = V); epilogue writes gathered go hi/lo
    attn_mma<<<dim3(SEQ / 128, BHD), 256, ATTN_SMEM>>>(1);
    // 5. Output projection, N=128
    out_mma<<<dim3(TOKENS / 128, DMODEL / 128), 256, projSmem>>>(bo, out);
}